// round 1
// baseline (speedup 1.0000x reference)
#include <cuda_runtime.h>
#include <math.h>

#define L_SEQ   2048
#define DMODEL  2048
#define NHEADS  16
#define HDIM    128
#define WINDOW  512
#define BROWS   4096   // B * L

// ---------------- scratch (no cudaMalloc allowed) ----------------
__device__ float g_q[BROWS * DMODEL];
__device__ float g_k[BROWS * HDIM];
__device__ float g_v[BROWS * HDIM];
__device__ float g_att[BROWS * DMODEL];
__device__ float g_cos[L_SEQ * 32];
__device__ float g_sin[L_SEQ * 32];

// ---------------- RoPE table (double-precision build, fp32 store) -----------
__global__ void rope_table_kernel() {
    int idx = blockIdx.x * blockDim.x + threadIdx.x;
    if (idx >= L_SEQ * 32) return;
    int pos = idx >> 5;
    int i = idx & 31;
    // inv_freq = exp(-log(10000) * (2i / 64))
    double inv = exp(-log(10000.0) * ((double)(2 * i) / 64.0));
    double th = (double)pos * inv;
    g_cos[idx] = (float)cos(th);
    g_sin[idx] = (float)sin(th);
}

// ---------------- generic 128x128x16 SGEMM, 8x8 per thread ----------------
__global__ void sgemm_kernel(const float* __restrict__ A,
                             const float* __restrict__ B,
                             const float* __restrict__ bias,
                             float* __restrict__ C,
                             int M, int N, int Kd) {
    __shared__ float As[16][128];   // transposed A tile: As[k][m]
    __shared__ float Bs[16][128];   // Bs[k][n]

    int tid = threadIdx.x;            // 256 threads
    int tx = tid & 15;
    int ty = tid >> 4;

    int arow = tid >> 2;              // 0..63
    int acol = (tid & 3) << 2;        // 0,4,8,12
    int brow = tid >> 5;              // 0..7
    int bcol = (tid & 31) << 2;       // 0..124

    const float* Ag = A + (size_t)(blockIdx.y * 128) * Kd;
    const float* Bg = B + blockIdx.x * 128;

    float acc[8][8];
    #pragma unroll
    for (int i = 0; i < 8; i++)
        #pragma unroll
        for (int j = 0; j < 8; j++) acc[i][j] = 0.0f;

    for (int k0 = 0; k0 < Kd; k0 += 16) {
        float4 a0 = *(const float4*)(Ag + (size_t)arow * Kd + k0 + acol);
        float4 a1 = *(const float4*)(Ag + (size_t)(arow + 64) * Kd + k0 + acol);
        As[acol + 0][arow] = a0.x; As[acol + 1][arow] = a0.y;
        As[acol + 2][arow] = a0.z; As[acol + 3][arow] = a0.w;
        As[acol + 0][arow + 64] = a1.x; As[acol + 1][arow + 64] = a1.y;
        As[acol + 2][arow + 64] = a1.z; As[acol + 3][arow + 64] = a1.w;

        *(float4*)&Bs[brow][bcol] =
            *(const float4*)(Bg + (size_t)(k0 + brow) * N + bcol);
        *(float4*)&Bs[brow + 8][bcol] =
            *(const float4*)(Bg + (size_t)(k0 + brow + 8) * N + bcol);

        __syncthreads();

        #pragma unroll
        for (int kk = 0; kk < 16; kk++) {
            float4 a4 = *(float4*)&As[kk][ty * 8];
            float4 a5 = *(float4*)&As[kk][ty * 8 + 4];
            float4 b4 = *(float4*)&Bs[kk][tx * 8];
            float4 b5 = *(float4*)&Bs[kk][tx * 8 + 4];
            float ra[8] = {a4.x, a4.y, a4.z, a4.w, a5.x, a5.y, a5.z, a5.w};
            float rb[8] = {b4.x, b4.y, b4.z, b4.w, b5.x, b5.y, b5.z, b5.w};
            #pragma unroll
            for (int i = 0; i < 8; i++)
                #pragma unroll
                for (int j = 0; j < 8; j++)
                    acc[i][j] += ra[i] * rb[j];
        }
        __syncthreads();
    }

    #pragma unroll
    for (int i = 0; i < 8; i++) {
        int row = blockIdx.y * 128 + ty * 8 + i;
        #pragma unroll
        for (int j = 0; j < 8; j += 4) {
            int col = blockIdx.x * 128 + tx * 8 + j;
            float4 vv;
            vv.x = acc[i][j + 0]; vv.y = acc[i][j + 1];
            vv.z = acc[i][j + 2]; vv.w = acc[i][j + 3];
            if (bias) {
                vv.x += bias[col + 0]; vv.y += bias[col + 1];
                vv.z += bias[col + 2]; vv.w += bias[col + 3];
            }
            *(float4*)&C[(size_t)row * N + col] = vv;
        }
    }
}

// ---------------- RoPE application ----------------
__global__ void rope_q_kernel() {
    int idx = blockIdx.x * blockDim.x + threadIdx.x;
    if (idx >= BROWS * NHEADS * 32) return;
    int m = idx >> 9;           // / (16*32)
    int rem = idx & 511;
    int h = rem >> 5;
    int c = rem & 31;
    int pos = m & (L_SEQ - 1);
    size_t base = (size_t)m * DMODEL + h * HDIM;
    float x1 = g_q[base + c];
    float x2 = g_q[base + c + 32];
    float co = g_cos[pos * 32 + c];
    float si = g_sin[pos * 32 + c];
    g_q[base + c]      = x1 * co - x2 * si;
    g_q[base + c + 32] = x1 * si + x2 * co;
}

__global__ void rope_k_kernel() {
    int idx = blockIdx.x * blockDim.x + threadIdx.x;
    if (idx >= BROWS * 32) return;
    int m = idx >> 5;
    int c = idx & 31;
    int pos = m & (L_SEQ - 1);
    size_t base = (size_t)m * HDIM;
    float x1 = g_k[base + c];
    float x2 = g_k[base + c + 32];
    float co = g_cos[pos * 32 + c];
    float si = g_sin[pos * 32 + c];
    g_k[base + c]      = x1 * co - x2 * si;
    g_k[base + c + 32] = x1 * si + x2 * co;
}

// ---------------- sliding-window flash attention ----------------
// grid: (L/64, NHEADS, B); 256 threads; dynamic smem 114688 B
__global__ void attn_kernel(const float* __restrict__ Q,
                            const float* __restrict__ Kg,
                            const float* __restrict__ Vg,
                            float* __restrict__ O) {
    constexpr int QT = 64, KT = 64;
    extern __shared__ float sm[];
    float* Qt = sm;              // [128][64]  (transposed)
    float* Kt = sm + 8192;       // [128][64]  (transposed)
    float* Vs = sm + 16384;      // [64][128]
    float* Ps = sm + 24576;      // [64][64]

    int qt = blockIdx.x, h = blockIdx.y, b = blockIdx.z;
    int qbase = qt * QT;
    int tid = threadIdx.x;
    int tx = tid & 15;
    int ty = tid >> 4;
    const float scale = 0.08838834764831845f;   // 1/sqrt(128)

    // load Q tile transposed (coalesced global float4, scalar smem stores)
    {
        int r0 = tid >> 5;               // 0..7
        int c4 = (tid & 31) << 2;        // 0..124
        #pragma unroll
        for (int rr = r0; rr < QT; rr += 8) {
            float4 g = *(const float4*)(Q + (size_t)(b * L_SEQ + qbase + rr) * DMODEL
                                          + h * HDIM + c4);
            Qt[(c4 + 0) * QT + rr] = g.x;
            Qt[(c4 + 1) * QT + rr] = g.y;
            Qt[(c4 + 2) * QT + rr] = g.z;
            Qt[(c4 + 3) * QT + rr] = g.w;
        }
    }

    float m_i[4], l_i[4], acc[4][8];
    #pragma unroll
    for (int i = 0; i < 4; i++) {
        m_i[i] = -1e30f;
        l_i[i] = 0.0f;
        #pragma unroll
        for (int c = 0; c < 8; c++) acc[i][c] = 0.0f;
    }

    int jlo = qbase - (WINDOW - 1);
    if (jlo < 0) jlo = 0;
    int t0 = jlo / KT;
    int t1 = (qbase + QT - 1) / KT;

    for (int t = t0; t <= t1; t++) {
        int kbase = t * KT;
        __syncthreads();   // protect smem from previous iteration / Q load done

        // load K (transposed) + V tiles
        {
            int r0 = tid >> 5;
            int c4 = (tid & 31) << 2;
            #pragma unroll
            for (int rr = r0; rr < KT; rr += 8) {
                size_t row = (size_t)(b * L_SEQ + kbase + rr);
                float4 gk = *(const float4*)(Kg + row * HDIM + c4);
                Kt[(c4 + 0) * KT + rr] = gk.x;
                Kt[(c4 + 1) * KT + rr] = gk.y;
                Kt[(c4 + 2) * KT + rr] = gk.z;
                Kt[(c4 + 3) * KT + rr] = gk.w;
                float4 gv = *(const float4*)(Vg + row * HDIM + c4);
                *(float4*)&Vs[rr * HDIM + c4] = gv;
            }
        }
        __syncthreads();

        // S = Q K^T  (each thread: 4 rows x 4 cols)
        float s[4][4];
        #pragma unroll
        for (int i = 0; i < 4; i++)
            #pragma unroll
            for (int j = 0; j < 4; j++) s[i][j] = 0.0f;

        #pragma unroll 4
        for (int kk = 0; kk < HDIM; kk++) {
            float4 q4 = *(float4*)&Qt[kk * QT + ty * 4];
            float4 k4 = *(float4*)&Kt[kk * KT + tx * 4];
            float qa[4] = {q4.x, q4.y, q4.z, q4.w};
            float kb[4] = {k4.x, k4.y, k4.z, k4.w};
            #pragma unroll
            for (int i = 0; i < 4; i++)
                #pragma unroll
                for (int j = 0; j < 4; j++)
                    s[i][j] += qa[i] * kb[j];
        }

        // mask + online softmax (rows owned by 16 lanes sharing ty)
        #pragma unroll
        for (int i = 0; i < 4; i++) {
            int gi = qbase + ty * 4 + i;
            float v[4];
            #pragma unroll
            for (int j = 0; j < 4; j++) {
                int gj = kbase + tx * 4 + j;
                int d = gi - gj;
                v[j] = s[i][j] * scale + ((d >= 0 && d < WINDOW) ? 0.0f : -1e9f);
            }
            float mt = fmaxf(fmaxf(v[0], v[1]), fmaxf(v[2], v[3]));
            #pragma unroll
            for (int o = 8; o; o >>= 1)
                mt = fmaxf(mt, __shfl_xor_sync(0xffffffffu, mt, o, 16));
            float m_new = fmaxf(m_i[i], mt);
            float corr = __expf(m_i[i] - m_new);
            float rs = 0.0f;
            #pragma unroll
            for (int j = 0; j < 4; j++) {
                float p = __expf(v[j] - m_new);
                rs += p;
                Ps[(ty * 4 + i) * KT + tx * 4 + j] = p;
            }
            #pragma unroll
            for (int o = 8; o; o >>= 1)
                rs += __shfl_xor_sync(0xffffffffu, rs, o, 16);
            l_i[i] = l_i[i] * corr + rs;
            m_i[i] = m_new;
            #pragma unroll
            for (int c = 0; c < 8; c++) acc[i][c] *= corr;
        }
        __syncthreads();   // Ps visible to all

        // O += P V   (thread: 4 rows x 8 cols)
        #pragma unroll 8
        for (int j = 0; j < KT; j++) {
            float p0 = Ps[(ty * 4 + 0) * KT + j];
            float p1 = Ps[(ty * 4 + 1) * KT + j];
            float p2 = Ps[(ty * 4 + 2) * KT + j];
            float p3 = Ps[(ty * 4 + 3) * KT + j];
            float4 v0 = *(float4*)&Vs[j * HDIM + tx * 8];
            float4 v1 = *(float4*)&Vs[j * HDIM + tx * 8 + 4];
            float vv[8] = {v0.x, v0.y, v0.z, v0.w, v1.x, v1.y, v1.z, v1.w};
            #pragma unroll
            for (int c = 0; c < 8; c++) {
                acc[0][c] += p0 * vv[c];
                acc[1][c] += p1 * vv[c];
                acc[2][c] += p2 * vv[c];
                acc[3][c] += p3 * vv[c];
            }
        }
    }

    // epilogue: normalize and store
    #pragma unroll
    for (int i = 0; i < 4; i++) {
        float inv = 1.0f / l_i[i];
        size_t row = (size_t)(b * L_SEQ + qbase + ty * 4 + i);
        float4 o0, o1;
        o0.x = acc[i][0] * inv; o0.y = acc[i][1] * inv;
        o0.z = acc[i][2] * inv; o0.w = acc[i][3] * inv;
        o1.x = acc[i][4] * inv; o1.y = acc[i][5] * inv;
        o1.z = acc[i][6] * inv; o1.w = acc[i][7] * inv;
        *(float4*)&O[row * DMODEL + h * HDIM + tx * 8]     = o0;
        *(float4*)&O[row * DMODEL + h * HDIM + tx * 8 + 4] = o1;
    }
}

// ---------------- launch ----------------
extern "C" void kernel_launch(void* const* d_in, const int* in_sizes, int n_in,
                              void* d_out, int out_size) {
    const float* x  = (const float*)d_in[0];
    const float* Wq = (const float*)d_in[1];
    const float* Wk = (const float*)d_in[2];
    const float* Wv = (const float*)d_in[3];
    const float* Wo = (const float*)d_in[4];
    const float* bo = (const float*)d_in[5];
    float* out = (float*)d_out;

    float *q, *k, *v, *att;
    cudaGetSymbolAddress((void**)&q,   g_q);
    cudaGetSymbolAddress((void**)&k,   g_k);
    cudaGetSymbolAddress((void**)&v,   g_v);
    cudaGetSymbolAddress((void**)&att, g_att);

    // RoPE tables
    rope_table_kernel<<<(L_SEQ * 32 + 255) / 256, 256>>>();

    // projections
    dim3 gq(DMODEL / 128, BROWS / 128);
    sgemm_kernel<<<gq, 256>>>(x, Wq, nullptr, q, BROWS, DMODEL, DMODEL);
    dim3 gkv(1, BROWS / 128);
    sgemm_kernel<<<gkv, 256>>>(x, Wk, nullptr, k, BROWS, HDIM, DMODEL);
    sgemm_kernel<<<gkv, 256>>>(x, Wv, nullptr, v, BROWS, HDIM, DMODEL);

    // RoPE
    rope_q_kernel<<<(BROWS * NHEADS * 32) / 256, 256>>>();
    rope_k_kernel<<<(BROWS * 32) / 256, 256>>>();

    // attention
    const int SMEM_BYTES = (8192 + 8192 + 8192 + 4096) * 4;   // 114688
    cudaFuncSetAttribute(attn_kernel,
                         cudaFuncAttributeMaxDynamicSharedMemorySize, SMEM_BYTES);
    dim3 ga(L_SEQ / 64, NHEADS, 2);
    attn_kernel<<<ga, 256, SMEM_BYTES>>>(q, k, v, att);

    // output projection + bias
    sgemm_kernel<<<gq, 256>>>(att, Wo, bo, out, BROWS, DMODEL, DMODEL);
}

// round 3
// speedup vs baseline: 1.5882x; 1.5882x over previous
#include <cuda_runtime.h>
#include <cuda_bf16.h>
#include <math.h>
#include <stdint.h>

#define L_SEQ   2048
#define DMODEL  2048
#define NHEADS  16
#define HDIM    128
#define WINDOW  512
#define BROWS   4096   // B * L
#define KDIM    2048

// ================= scratch =================
__device__ float g_q[BROWS * DMODEL];
__device__ float g_kv[BROWS * 256];     // K at cols 0..127, V at 128..255
__device__ float g_att[BROWS * DMODEL];
__device__ float g_cos[L_SEQ * 32];
__device__ float g_sin[L_SEQ * 32];
__device__ __nv_bfloat16 g_xh[BROWS * DMODEL];
__device__ __nv_bfloat16 g_xl[BROWS * DMODEL];
__device__ __nv_bfloat16 g_ath[BROWS * DMODEL];
__device__ __nv_bfloat16 g_atl[BROWS * DMODEL];
__device__ __nv_bfloat16 g_wqt_h[DMODEL * KDIM];
__device__ __nv_bfloat16 g_wqt_l[DMODEL * KDIM];
__device__ __nv_bfloat16 g_wot_h[DMODEL * KDIM];
__device__ __nv_bfloat16 g_wot_l[DMODEL * KDIM];
__device__ __nv_bfloat16 g_wkvt_h[256 * KDIM];
__device__ __nv_bfloat16 g_wkvt_l[256 * KDIM];

// ================= helpers =================
__device__ __forceinline__ uint32_t smem_u32(const void* p) {
    uint32_t a;
    asm("{ .reg .u64 t; cvta.to.shared.u64 t, %1; cvt.u32.u64 %0, t; }" : "=r"(a) : "l"(p));
    return a;
}
#define CP_ASYNC16(saddr, gptr) \
    asm volatile("cp.async.cg.shared.global [%0], [%1], 16;" :: "r"(saddr), "l"(gptr))
#define CP_COMMIT()  asm volatile("cp.async.commit_group;" ::: "memory")
#define CP_WAIT0()   asm volatile("cp.async.wait_group 0;" ::: "memory")
#define CP_WAIT1()   asm volatile("cp.async.wait_group 1;" ::: "memory")

#define LDMATRIX_X4(r0, r1, r2, r3, addr) \
    asm volatile("ldmatrix.sync.aligned.m8n8.x4.shared.b16 {%0,%1,%2,%3}, [%4];" \
        : "=r"(r0), "=r"(r1), "=r"(r2), "=r"(r3) : "r"(addr))

#define MMA_BF16(c, a, b) \
    asm volatile("mma.sync.aligned.m16n8k16.row.col.f32.bf16.bf16.f32 " \
        "{%0,%1,%2,%3}, {%4,%5,%6,%7}, {%8,%9}, {%0,%1,%2,%3};" \
        : "+f"((c)[0]), "+f"((c)[1]), "+f"((c)[2]), "+f"((c)[3]) \
        : "r"((a)[0]), "r"((a)[1]), "r"((a)[2]), "r"((a)[3]), "r"((b)[0]), "r"((b)[1]))

// ================= small prep kernels =================
__global__ void rope_table_kernel() {
    int idx = blockIdx.x * blockDim.x + threadIdx.x;
    if (idx >= L_SEQ * 32) return;
    int pos = idx >> 5;
    int i = idx & 31;
    double inv = exp(-log(10000.0) * ((double)(2 * i) / 64.0));
    double th = (double)pos * inv;
    g_cos[idx] = (float)cos(th);
    g_sin[idx] = (float)sin(th);
}

__global__ void split_kernel(const float* __restrict__ in,
                             __nv_bfloat16* __restrict__ hi,
                             __nv_bfloat16* __restrict__ lo, int n) {
    int idx = blockIdx.x * blockDim.x + threadIdx.x;
    if (idx >= n) return;
    float v = in[idx];
    __nv_bfloat16 h = __float2bfloat16(v);
    hi[idx] = h;
    lo[idx] = __float2bfloat16(v - __bfloat162float(h));
}

// W [K][N] fp32 -> Th/Tl [ro+N][KDIM] bf16 (transposed + split)
__global__ void tsplit_kernel(const float* __restrict__ W,
                              __nv_bfloat16* __restrict__ Th,
                              __nv_bfloat16* __restrict__ Tl,
                              int N, int ro) {
    __shared__ float tile[32][33];
    int n0 = blockIdx.x * 32, k0 = blockIdx.y * 32;
    int tx = threadIdx.x, ty = threadIdx.y;  // 32 x 8
    #pragma unroll
    for (int i = ty; i < 32; i += 8)
        tile[i][tx] = W[(size_t)(k0 + i) * N + n0 + tx];
    __syncthreads();
    #pragma unroll
    for (int i = ty; i < 32; i += 8) {
        float v = tile[tx][i];
        __nv_bfloat16 h = __float2bfloat16(v);
        size_t o = (size_t)(ro + n0 + i) * KDIM + k0 + tx;
        Th[o] = h;
        Tl[o] = __float2bfloat16(v - __bfloat162float(h));
    }
}

// ================= mma.sync bf16 GEMM =================
// C[M, Nout] = A[M, 2048] * Bt[N, 2048]^T (+bias), 3-pass hi/lo split.
// grid (Nout/128, M/128), 256 threads, dyn smem 65536 (2-stage double buffer).
//
// smem tile layout: per matrix 128x32 bf16 as 8x8-b16 tiles, tile (Tm,Tk)
// contiguous 128B at ((Tm*4+Tk)*128); within tile, row r stored at slot
// (r ^ Tk) to make cp.async fills bank-conflict-free; ldmatrix readers use
// the same xor in per-thread row addresses.
__global__ void __launch_bounds__(256, 2)
gemm_bf16_kernel(const __nv_bfloat16* __restrict__ Ah,
                 const __nv_bfloat16* __restrict__ Al,
                 const __nv_bfloat16* __restrict__ Bth,
                 const __nv_bfloat16* __restrict__ Btl,
                 const float* __restrict__ bias,
                 float* __restrict__ C, int Nout) {
    extern __shared__ char smem[];
    const uint32_t smb = smem_u32(smem);
    const int tid = threadIdx.x;
    const int wid = tid >> 5;
    const int lane = tid & 31;
    const int wm = wid >> 2;          // 0..1 (64 rows each)
    const int wn = wid & 3;           // 0..3 (32 cols each)
    const uint32_t midx = lane >> 3;  // ldmatrix matrix index
    const uint32_t rsel = lane & 7;   // ldmatrix row index

    const int m0 = blockIdx.y * 128;
    const int n0 = blockIdx.x * 128;
    const __nv_bfloat16* srcs[4] = {
        Ah + (size_t)m0 * KDIM, Al + (size_t)m0 * KDIM,
        Bth + (size_t)n0 * KDIM, Btl + (size_t)n0 * KDIM };

    // fill indices
    const int fr = tid >> 2;                // 0..63
    const uint32_t fkt = (uint32_t)(tid & 3);
    const int fc0 = (tid & 3) * 8;

    float acc[4][4][4];
    #pragma unroll
    for (int i = 0; i < 4; i++)
        #pragma unroll
        for (int j = 0; j < 4; j++)
            #pragma unroll
            for (int c = 0; c < 4; c++) acc[i][j][c] = 0.0f;

    // prefetch chunk 0
    #pragma unroll
    for (int m = 0; m < 4; m++) {
        #pragma unroll
        for (int half = 0; half < 2; half++) {
            int rr = fr + half * 64;
            uint32_t off = ((uint32_t)(rr >> 3) * 4 + fkt) * 128
                         + ((uint32_t)((rr & 7) ^ fkt) * 16);
            CP_ASYNC16(smb + m * 8192 + off, srcs[m] + (size_t)rr * KDIM + fc0);
        }
    }
    CP_COMMIT();

    const int NK = KDIM / 32;
    for (int kc = 0; kc < NK; kc++) {
        if (kc + 1 < NK) {
            uint32_t sb = smb + ((kc + 1) & 1) * 32768;
            #pragma unroll
            for (int m = 0; m < 4; m++) {
                #pragma unroll
                for (int half = 0; half < 2; half++) {
                    int rr = fr + half * 64;
                    uint32_t off = ((uint32_t)(rr >> 3) * 4 + fkt) * 128
                                 + ((uint32_t)((rr & 7) ^ fkt) * 16);
                    CP_ASYNC16(sb + m * 8192 + off,
                               srcs[m] + (size_t)rr * KDIM + (kc + 1) * 32 + fc0);
                }
            }
            CP_COMMIT();
            CP_WAIT1();
        } else {
            CP_WAIT0();
        }
        __syncthreads();

        const uint32_t sb = smb + (kc & 1) * 32768;
        const uint32_t aBaseH = sb;
        const uint32_t aBaseL = sb + 8192;
        const uint32_t bBaseH = sb + 16384;
        const uint32_t bBaseL = sb + 24576;

        #pragma unroll
        for (int kt = 0; kt < 2; kt++) {
            uint32_t aF[4][4], bH[4][2], bL[4][2];
            // A hi fragments (4 x m16)
            #pragma unroll
            for (int mi = 0; mi < 4; mi++) {
                uint32_t Tm = (uint32_t)(wm * 8 + mi * 2) + (midx & 1);
                uint32_t Tk = (uint32_t)(kt * 2) + (midx >> 1);
                uint32_t addr = aBaseH + (Tm * 4 + Tk) * 128 + ((rsel ^ Tk) * 16);
                LDMATRIX_X4(aF[mi][0], aF[mi][1], aF[mi][2], aF[mi][3], addr);
            }
            // B hi fragments (4 x n8)
            #pragma unroll
            for (int nj = 0; nj < 2; nj++) {
                uint32_t Tn = (uint32_t)(wn * 4 + nj * 2) + (midx >> 1);
                uint32_t Tk = (uint32_t)(kt * 2) + (midx & 1);
                uint32_t addr = bBaseH + (Tn * 4 + Tk) * 128 + ((rsel ^ Tk) * 16);
                uint32_t r0, r1, r2, r3;
                LDMATRIX_X4(r0, r1, r2, r3, addr);
                bH[nj * 2][0] = r0; bH[nj * 2][1] = r1;
                bH[nj * 2 + 1][0] = r2; bH[nj * 2 + 1][1] = r3;
            }
            // pass hh
            #pragma unroll
            for (int mi = 0; mi < 4; mi++)
                #pragma unroll
                for (int ni = 0; ni < 4; ni++)
                    MMA_BF16(acc[mi][ni], aF[mi], bH[ni]);
            // B lo fragments
            #pragma unroll
            for (int nj = 0; nj < 2; nj++) {
                uint32_t Tn = (uint32_t)(wn * 4 + nj * 2) + (midx >> 1);
                uint32_t Tk = (uint32_t)(kt * 2) + (midx & 1);
                uint32_t addr = bBaseL + (Tn * 4 + Tk) * 128 + ((rsel ^ Tk) * 16);
                uint32_t r0, r1, r2, r3;
                LDMATRIX_X4(r0, r1, r2, r3, addr);
                bL[nj * 2][0] = r0; bL[nj * 2][1] = r1;
                bL[nj * 2 + 1][0] = r2; bL[nj * 2 + 1][1] = r3;
            }
            // pass hl
            #pragma unroll
            for (int mi = 0; mi < 4; mi++)
                #pragma unroll
                for (int ni = 0; ni < 4; ni++)
                    MMA_BF16(acc[mi][ni], aF[mi], bL[ni]);
            // A lo fragments (overwrite aF)
            #pragma unroll
            for (int mi = 0; mi < 4; mi++) {
                uint32_t Tm = (uint32_t)(wm * 8 + mi * 2) + (midx & 1);
                uint32_t Tk = (uint32_t)(kt * 2) + (midx >> 1);
                uint32_t addr = aBaseL + (Tm * 4 + Tk) * 128 + ((rsel ^ Tk) * 16);
                LDMATRIX_X4(aF[mi][0], aF[mi][1], aF[mi][2], aF[mi][3], addr);
            }
            // pass lh
            #pragma unroll
            for (int mi = 0; mi < 4; mi++)
                #pragma unroll
                for (int ni = 0; ni < 4; ni++)
                    MMA_BF16(acc[mi][ni], aF[mi], bH[ni]);
        }
        __syncthreads();
    }

    // epilogue
    #pragma unroll
    for (int mi = 0; mi < 4; mi++) {
        int row = m0 + wm * 64 + mi * 16 + (lane >> 2);
        #pragma unroll
        for (int ni = 0; ni < 4; ni++) {
            int col = n0 + wn * 32 + ni * 8 + (lane & 3) * 2;
            float b0 = 0.f, b1 = 0.f;
            if (bias) { b0 = bias[col]; b1 = bias[col + 1]; }
            float2 v0, v1;
            v0.x = acc[mi][ni][0] + b0; v0.y = acc[mi][ni][1] + b1;
            v1.x = acc[mi][ni][2] + b0; v1.y = acc[mi][ni][3] + b1;
            *(float2*)&C[(size_t)row * Nout + col] = v0;
            *(float2*)&C[(size_t)(row + 8) * Nout + col] = v1;
        }
    }
}

// ================= RoPE =================
__global__ void rope_q_kernel() {
    int idx = blockIdx.x * blockDim.x + threadIdx.x;
    if (idx >= BROWS * NHEADS * 32) return;
    int m = idx >> 9;
    int rem = idx & 511;
    int h = rem >> 5;
    int c = rem & 31;
    int pos = m & (L_SEQ - 1);
    size_t base = (size_t)m * DMODEL + h * HDIM;
    float x1 = g_q[base + c];
    float x2 = g_q[base + c + 32];
    float co = g_cos[pos * 32 + c];
    float si = g_sin[pos * 32 + c];
    g_q[base + c]      = x1 * co - x2 * si;
    g_q[base + c + 32] = x1 * si + x2 * co;
}

__global__ void rope_k_kernel() {
    int idx = blockIdx.x * blockDim.x + threadIdx.x;
    if (idx >= BROWS * 32) return;
    int m = idx >> 5;
    int c = idx & 31;
    int pos = m & (L_SEQ - 1);
    size_t base = (size_t)m * 256;
    float x1 = g_kv[base + c];
    float x2 = g_kv[base + c + 32];
    float co = g_cos[pos * 32 + c];
    float si = g_sin[pos * 32 + c];
    g_kv[base + c]      = x1 * co - x2 * si;
    g_kv[base + c + 32] = x1 * si + x2 * co;
}

// ================= sliding-window flash attention (fp32 SIMT) =================
__global__ void attn_kernel(const float* __restrict__ Q,
                            const float* __restrict__ Kg,   // stride 256
                            const float* __restrict__ Vg,   // stride 256
                            float* __restrict__ O) {
    constexpr int QT = 64, KT = 64;
    extern __shared__ float sm[];
    float* Qt = sm;              // [128][64]
    float* Kt = sm + 8192;       // [128][64]
    float* Vs = sm + 16384;      // [64][128]
    float* Ps = sm + 24576;      // [64][64]

    int qt = blockIdx.x, h = blockIdx.y, b = blockIdx.z;
    int qbase = qt * QT;
    int tid = threadIdx.x;
    int tx = tid & 15;
    int ty = tid >> 4;
    const float scale = 0.08838834764831845f;

    {
        int r0 = tid >> 5;
        int c4 = (tid & 31) << 2;
        #pragma unroll
        for (int rr = r0; rr < QT; rr += 8) {
            float4 g = *(const float4*)(Q + (size_t)(b * L_SEQ + qbase + rr) * DMODEL
                                          + h * HDIM + c4);
            Qt[(c4 + 0) * QT + rr] = g.x;
            Qt[(c4 + 1) * QT + rr] = g.y;
            Qt[(c4 + 2) * QT + rr] = g.z;
            Qt[(c4 + 3) * QT + rr] = g.w;
        }
    }

    float m_i[4], l_i[4], acc[4][8];
    #pragma unroll
    for (int i = 0; i < 4; i++) {
        m_i[i] = -1e30f; l_i[i] = 0.0f;
        #pragma unroll
        for (int c = 0; c < 8; c++) acc[i][c] = 0.0f;
    }

    int jlo = qbase - (WINDOW - 1);
    if (jlo < 0) jlo = 0;
    int t0 = jlo / KT;
    int t1 = (qbase + QT - 1) / KT;

    for (int t = t0; t <= t1; t++) {
        int kbase = t * KT;
        __syncthreads();
        {
            int r0 = tid >> 5;
            int c4 = (tid & 31) << 2;
            #pragma unroll
            for (int rr = r0; rr < KT; rr += 8) {
                size_t row = (size_t)(b * L_SEQ + kbase + rr);
                float4 gk = *(const float4*)(Kg + row * 256 + c4);
                Kt[(c4 + 0) * KT + rr] = gk.x;
                Kt[(c4 + 1) * KT + rr] = gk.y;
                Kt[(c4 + 2) * KT + rr] = gk.z;
                Kt[(c4 + 3) * KT + rr] = gk.w;
                float4 gv = *(const float4*)(Vg + row * 256 + c4);
                *(float4*)&Vs[rr * HDIM + c4] = gv;
            }
        }
        __syncthreads();

        float s[4][4];
        #pragma unroll
        for (int i = 0; i < 4; i++)
            #pragma unroll
            for (int j = 0; j < 4; j++) s[i][j] = 0.0f;

        #pragma unroll 4
        for (int kk = 0; kk < HDIM; kk++) {
            float4 q4 = *(float4*)&Qt[kk * QT + ty * 4];
            float4 k4 = *(float4*)&Kt[kk * KT + tx * 4];
            float qa[4] = {q4.x, q4.y, q4.z, q4.w};
            float kb[4] = {k4.x, k4.y, k4.z, k4.w};
            #pragma unroll
            for (int i = 0; i < 4; i++)
                #pragma unroll
                for (int j = 0; j < 4; j++)
                    s[i][j] += qa[i] * kb[j];
        }

        #pragma unroll
        for (int i = 0; i < 4; i++) {
            int gi = qbase + ty * 4 + i;
            float v[4];
            #pragma unroll
            for (int j = 0; j < 4; j++) {
                int gj = kbase + tx * 4 + j;
                int d = gi - gj;
                v[j] = s[i][j] * scale + ((d >= 0 && d < WINDOW) ? 0.0f : -1e9f);
            }
            float mt = fmaxf(fmaxf(v[0], v[1]), fmaxf(v[2], v[3]));
            #pragma unroll
            for (int o = 8; o; o >>= 1)
                mt = fmaxf(mt, __shfl_xor_sync(0xffffffffu, mt, o, 16));
            float m_new = fmaxf(m_i[i], mt);
            float corr = __expf(m_i[i] - m_new);
            float rs = 0.0f;
            #pragma unroll
            for (int j = 0; j < 4; j++) {
                float p = __expf(v[j] - m_new);
                rs += p;
                Ps[(ty * 4 + i) * KT + tx * 4 + j] = p;
            }
            #pragma unroll
            for (int o = 8; o; o >>= 1)
                rs += __shfl_xor_sync(0xffffffffu, rs, o, 16);
            l_i[i] = l_i[i] * corr + rs;
            m_i[i] = m_new;
            #pragma unroll
            for (int c = 0; c < 8; c++) acc[i][c] *= corr;
        }
        __syncthreads();

        #pragma unroll 8
        for (int j = 0; j < KT; j++) {
            float p0 = Ps[(ty * 4 + 0) * KT + j];
            float p1 = Ps[(ty * 4 + 1) * KT + j];
            float p2 = Ps[(ty * 4 + 2) * KT + j];
            float p3 = Ps[(ty * 4 + 3) * KT + j];
            float4 v0 = *(float4*)&Vs[j * HDIM + tx * 8];
            float4 v1 = *(float4*)&Vs[j * HDIM + tx * 8 + 4];
            float vv[8] = {v0.x, v0.y, v0.z, v0.w, v1.x, v1.y, v1.z, v1.w};
            #pragma unroll
            for (int c = 0; c < 8; c++) {
                acc[0][c] += p0 * vv[c];
                acc[1][c] += p1 * vv[c];
                acc[2][c] += p2 * vv[c];
                acc[3][c] += p3 * vv[c];
            }
        }
    }

    #pragma unroll
    for (int i = 0; i < 4; i++) {
        float inv = 1.0f / l_i[i];
        size_t row = (size_t)(b * L_SEQ + qbase + ty * 4 + i);
        float4 o0, o1;
        o0.x = acc[i][0] * inv; o0.y = acc[i][1] * inv;
        o0.z = acc[i][2] * inv; o0.w = acc[i][3] * inv;
        o1.x = acc[i][4] * inv; o1.y = acc[i][5] * inv;
        o1.z = acc[i][6] * inv; o1.w = acc[i][7] * inv;
        *(float4*)&O[row * DMODEL + h * HDIM + tx * 8]     = o0;
        *(float4*)&O[row * DMODEL + h * HDIM + tx * 8 + 4] = o1;
    }
}

// ================= launch =================
extern "C" void kernel_launch(void* const* d_in, const int* in_sizes, int n_in,
                              void* d_out, int out_size) {
    const float* x  = (const float*)d_in[0];
    const float* Wq = (const float*)d_in[1];
    const float* Wk = (const float*)d_in[2];
    const float* Wv = (const float*)d_in[3];
    const float* Wo = (const float*)d_in[4];
    const float* bo = (const float*)d_in[5];
    float* out = (float*)d_out;

    float *q, *kv, *att;
    __nv_bfloat16 *xh, *xl, *ath, *atl, *wqh, *wql, *woh, *wol, *wkvh, *wkvl;
    cudaGetSymbolAddress((void**)&q,   g_q);
    cudaGetSymbolAddress((void**)&kv,  g_kv);
    cudaGetSymbolAddress((void**)&att, g_att);
    cudaGetSymbolAddress((void**)&xh,  g_xh);
    cudaGetSymbolAddress((void**)&xl,  g_xl);
    cudaGetSymbolAddress((void**)&ath, g_ath);
    cudaGetSymbolAddress((void**)&atl, g_atl);
    cudaGetSymbolAddress((void**)&wqh, g_wqt_h);
    cudaGetSymbolAddress((void**)&wql, g_wqt_l);
    cudaGetSymbolAddress((void**)&woh, g_wot_h);
    cudaGetSymbolAddress((void**)&wol, g_wot_l);
    cudaGetSymbolAddress((void**)&wkvh, g_wkvt_h);
    cudaGetSymbolAddress((void**)&wkvl, g_wkvt_l);

    const int GEMM_SMEM = 65536;
    cudaFuncSetAttribute(gemm_bf16_kernel,
                         cudaFuncAttributeMaxDynamicSharedMemorySize, GEMM_SMEM);

    // prep
    rope_table_kernel<<<(L_SEQ * 32 + 255) / 256, 256>>>();
    split_kernel<<<(BROWS * DMODEL) / 256, 256>>>(x, xh, xl, BROWS * DMODEL);
    dim3 tb(32, 8);
    tsplit_kernel<<<dim3(DMODEL / 32, KDIM / 32), tb>>>(Wq, wqh, wql, DMODEL, 0);
    tsplit_kernel<<<dim3(HDIM / 32, KDIM / 32), tb>>>(Wk, wkvh, wkvl, HDIM, 0);
    tsplit_kernel<<<dim3(HDIM / 32, KDIM / 32), tb>>>(Wv, wkvh, wkvl, HDIM, 128);
    tsplit_kernel<<<dim3(DMODEL / 32, KDIM / 32), tb>>>(Wo, woh, wol, DMODEL, 0);

    // projections on tensor cores (mma.sync HMMA)
    gemm_bf16_kernel<<<dim3(DMODEL / 128, BROWS / 128), 256, GEMM_SMEM>>>(
        xh, xl, wqh, wql, nullptr, q, DMODEL);
    gemm_bf16_kernel<<<dim3(2, BROWS / 128), 256, GEMM_SMEM>>>(
        xh, xl, wkvh, wkvl, nullptr, kv, 256);

    // RoPE
    rope_q_kernel<<<(BROWS * NHEADS * 32) / 256, 256>>>();
    rope_k_kernel<<<(BROWS * 32) / 256, 256>>>();

    // attention
    const int ATTN_SMEM = (8192 + 8192 + 8192 + 4096) * 4;
    cudaFuncSetAttribute(attn_kernel,
                         cudaFuncAttributeMaxDynamicSharedMemorySize, ATTN_SMEM);
    dim3 ga(L_SEQ / 64, NHEADS, 2);
    attn_kernel<<<ga, 256, ATTN_SMEM>>>(q, kv, kv + 128, att);

    // output projection
    split_kernel<<<(BROWS * DMODEL) / 256, 256>>>(att, ath, atl, BROWS * DMODEL);
    gemm_bf16_kernel<<<dim3(DMODEL / 128, BROWS / 128), 256, GEMM_SMEM>>>(
        ath, atl, woh, wol, bo, out, DMODEL);
}

// round 4
// speedup vs baseline: 2.5966x; 1.6350x over previous
#include <cuda_runtime.h>
#include <cuda_bf16.h>
#include <math.h>
#include <stdint.h>

#define L_SEQ   2048
#define DMODEL  2048
#define NHEADS  16
#define HDIM    128
#define WINDOW  512
#define BROWS   4096   // B * L
#define KDIM    2048

// ================= scratch =================
__device__ float g_q[BROWS * DMODEL];
__device__ float g_kv[BROWS * 256];     // K cols 0..127, V cols 128..255
__device__ float g_cos[L_SEQ * 32];
__device__ float g_sin[L_SEQ * 32];
__device__ __nv_bfloat16 g_xh[BROWS * DMODEL];
__device__ __nv_bfloat16 g_xl[BROWS * DMODEL];
__device__ __nv_bfloat16 g_qh[BROWS * DMODEL];
__device__ __nv_bfloat16 g_ql[BROWS * DMODEL];
__device__ __nv_bfloat16 g_kh[BROWS * HDIM];
__device__ __nv_bfloat16 g_kl[BROWS * HDIM];
__device__ __nv_bfloat16 g_vh[BROWS * HDIM];
__device__ __nv_bfloat16 g_vl[BROWS * HDIM];
__device__ __nv_bfloat16 g_ath[BROWS * DMODEL];
__device__ __nv_bfloat16 g_atl[BROWS * DMODEL];
__device__ __nv_bfloat16 g_wqt_h[DMODEL * KDIM];
__device__ __nv_bfloat16 g_wqt_l[DMODEL * KDIM];
__device__ __nv_bfloat16 g_wot_h[DMODEL * KDIM];
__device__ __nv_bfloat16 g_wot_l[DMODEL * KDIM];
__device__ __nv_bfloat16 g_wkvt_h[256 * KDIM];
__device__ __nv_bfloat16 g_wkvt_l[256 * KDIM];

// ================= helpers =================
__device__ __forceinline__ uint32_t smem_u32(const void* p) {
    uint32_t a;
    asm("{ .reg .u64 t; cvta.to.shared.u64 t, %1; cvt.u32.u64 %0, t; }" : "=r"(a) : "l"(p));
    return a;
}
#define CP_ASYNC16(saddr, gptr) \
    asm volatile("cp.async.cg.shared.global [%0], [%1], 16;" :: "r"(saddr), "l"(gptr))
#define CP_COMMIT()  asm volatile("cp.async.commit_group;" ::: "memory")
#define CP_WAIT0()   asm volatile("cp.async.wait_group 0;" ::: "memory")
#define CP_WAIT1()   asm volatile("cp.async.wait_group 1;" ::: "memory")

#define LDMATRIX_X4(r0, r1, r2, r3, addr) \
    asm volatile("ldmatrix.sync.aligned.m8n8.x4.shared.b16 {%0,%1,%2,%3}, [%4];" \
        : "=r"(r0), "=r"(r1), "=r"(r2), "=r"(r3) : "r"(addr))

#define LDMATRIX_X4_T(r0, r1, r2, r3, addr) \
    asm volatile("ldmatrix.sync.aligned.m8n8.x4.trans.shared.b16 {%0,%1,%2,%3}, [%4];" \
        : "=r"(r0), "=r"(r1), "=r"(r2), "=r"(r3) : "r"(addr))

#define MMA_BF16(c, a, b) \
    asm volatile("mma.sync.aligned.m16n8k16.row.col.f32.bf16.bf16.f32 " \
        "{%0,%1,%2,%3}, {%4,%5,%6,%7}, {%8,%9}, {%0,%1,%2,%3};" \
        : "+f"((c)[0]), "+f"((c)[1]), "+f"((c)[2]), "+f"((c)[3]) \
        : "r"((a)[0]), "r"((a)[1]), "r"((a)[2]), "r"((a)[3]), "r"((b)[0]), "r"((b)[1]))

__device__ __forceinline__ void split_store(float v, __nv_bfloat16* H, __nv_bfloat16* L, size_t o) {
    __nv_bfloat16 h = __float2bfloat16(v);
    H[o] = h;
    L[o] = __float2bfloat16(v - __bfloat162float(h));
}

// ================= small prep kernels =================
__global__ void rope_table_kernel() {
    int idx = blockIdx.x * blockDim.x + threadIdx.x;
    if (idx >= L_SEQ * 32) return;
    int pos = idx >> 5;
    int i = idx & 31;
    double inv = exp(-log(10000.0) * ((double)(2 * i) / 64.0));
    double th = (double)pos * inv;
    g_cos[idx] = (float)cos(th);
    g_sin[idx] = (float)sin(th);
}

__global__ void split_kernel(const float* __restrict__ in,
                             __nv_bfloat16* __restrict__ hi,
                             __nv_bfloat16* __restrict__ lo, int n) {
    int idx = blockIdx.x * blockDim.x + threadIdx.x;
    if (idx >= n) return;
    float v = in[idx];
    __nv_bfloat16 h = __float2bfloat16(v);
    hi[idx] = h;
    lo[idx] = __float2bfloat16(v - __bfloat162float(h));
}

// W [K][N] fp32 -> Th/Tl [ro+N][KDIM] bf16 (transposed + split)
__global__ void tsplit_kernel(const float* __restrict__ W,
                              __nv_bfloat16* __restrict__ Th,
                              __nv_bfloat16* __restrict__ Tl,
                              int N, int ro) {
    __shared__ float tile[32][33];
    int n0 = blockIdx.x * 32, k0 = blockIdx.y * 32;
    int tx = threadIdx.x, ty = threadIdx.y;  // 32 x 8
    #pragma unroll
    for (int i = ty; i < 32; i += 8)
        tile[i][tx] = W[(size_t)(k0 + i) * N + n0 + tx];
    __syncthreads();
    #pragma unroll
    for (int i = ty; i < 32; i += 8) {
        float v = tile[tx][i];
        __nv_bfloat16 h = __float2bfloat16(v);
        size_t o = (size_t)(ro + n0 + i) * KDIM + k0 + tx;
        Th[o] = h;
        Tl[o] = __float2bfloat16(v - __bfloat162float(h));
    }
}

// RoPE on Q (fp32) -> bf16 hi/lo
__global__ void rope_split_q_kernel() {
    int idx = blockIdx.x * blockDim.x + threadIdx.x;
    if (idx >= BROWS * NHEADS * 64) return;
    int m = idx >> 10;
    int rem = idx & 1023;
    int h = rem >> 6;
    int c = rem & 63;
    int pos = m & (L_SEQ - 1);
    size_t base = (size_t)m * DMODEL + h * HDIM;
    if (c < 32) {
        float x1 = g_q[base + c], x2 = g_q[base + c + 32];
        float co = g_cos[pos * 32 + c], si = g_sin[pos * 32 + c];
        split_store(x1 * co - x2 * si, g_qh, g_ql, base + c);
        split_store(x1 * si + x2 * co, g_qh, g_ql, base + c + 32);
    } else {
        split_store(g_q[base + c + 32], g_qh, g_ql, base + c + 32);
        split_store(g_q[base + c + 64], g_qh, g_ql, base + c + 64);
    }
}

// RoPE on K + split K,V (from fp32 g_kv, stride 256) -> bf16 hi/lo stride 128
__global__ void rope_split_kv_kernel() {
    int idx = blockIdx.x * blockDim.x + threadIdx.x;
    if (idx >= BROWS * 64) return;
    int m = idx >> 6;
    int c = idx & 63;
    int pos = m & (L_SEQ - 1);
    size_t kvb = (size_t)m * 256;
    size_t ob = (size_t)m * HDIM;
    if (c < 32) {
        float x1 = g_kv[kvb + c], x2 = g_kv[kvb + c + 32];
        float co = g_cos[pos * 32 + c], si = g_sin[pos * 32 + c];
        split_store(x1 * co - x2 * si, g_kh, g_kl, ob + c);
        split_store(x1 * si + x2 * co, g_kh, g_kl, ob + c + 32);
    } else {
        split_store(g_kv[kvb + c + 32], g_kh, g_kl, ob + c + 32);
        split_store(g_kv[kvb + c + 64], g_kh, g_kl, ob + c + 64);
    }
    split_store(g_kv[kvb + 128 + c], g_vh, g_vl, ob + c);
    split_store(g_kv[kvb + 192 + c], g_vh, g_vl, ob + c + 64);
}

// ================= mma.sync bf16 GEMM (dual output set) =================
__global__ void __launch_bounds__(256, 2)
gemm_bf16_kernel(const __nv_bfloat16* __restrict__ Ah,
                 const __nv_bfloat16* __restrict__ Al,
                 const __nv_bfloat16* __restrict__ B1h,
                 const __nv_bfloat16* __restrict__ B1l,
                 const float* __restrict__ bias1,
                 float* __restrict__ C1, int N1, int nx1,
                 const __nv_bfloat16* __restrict__ B2h,
                 const __nv_bfloat16* __restrict__ B2l,
                 float* __restrict__ C2, int N2) {
    extern __shared__ char smem[];
    const uint32_t smb = smem_u32(smem);
    const int tid = threadIdx.x;
    const int wid = tid >> 5;
    const int lane = tid & 31;
    const int wm = wid >> 2;
    const int wn = wid & 3;
    const uint32_t midx = lane >> 3;
    const uint32_t rsel = lane & 7;

    const int m0 = blockIdx.y * 128;
    const __nv_bfloat16* Bh;
    const __nv_bfloat16* Bl;
    const float* bias;
    float* C;
    int Nout, n0;
    if ((int)blockIdx.x < nx1) {
        n0 = blockIdx.x * 128; Bh = B1h; Bl = B1l; bias = bias1; C = C1; Nout = N1;
    } else {
        n0 = (blockIdx.x - nx1) * 128; Bh = B2h; Bl = B2l; bias = nullptr; C = C2; Nout = N2;
    }
    const __nv_bfloat16* srcs[4] = {
        Ah + (size_t)m0 * KDIM, Al + (size_t)m0 * KDIM,
        Bh + (size_t)n0 * KDIM, Bl + (size_t)n0 * KDIM };

    const int fr = tid >> 2;
    const uint32_t fkt = (uint32_t)(tid & 3);
    const int fc0 = (tid & 3) * 8;

    float acc[4][4][4];
    #pragma unroll
    for (int i = 0; i < 4; i++)
        #pragma unroll
        for (int j = 0; j < 4; j++)
            #pragma unroll
            for (int c = 0; c < 4; c++) acc[i][j][c] = 0.0f;

    #pragma unroll
    for (int m = 0; m < 4; m++)
        #pragma unroll
        for (int half = 0; half < 2; half++) {
            int rr = fr + half * 64;
            uint32_t off = ((uint32_t)(rr >> 3) * 4 + fkt) * 128
                         + ((uint32_t)((rr & 7) ^ fkt) * 16);
            CP_ASYNC16(smb + m * 8192 + off, srcs[m] + (size_t)rr * KDIM + fc0);
        }
    CP_COMMIT();

    const int NK = KDIM / 32;
    for (int kc = 0; kc < NK; kc++) {
        if (kc + 1 < NK) {
            uint32_t sb = smb + ((kc + 1) & 1) * 32768;
            #pragma unroll
            for (int m = 0; m < 4; m++)
                #pragma unroll
                for (int half = 0; half < 2; half++) {
                    int rr = fr + half * 64;
                    uint32_t off = ((uint32_t)(rr >> 3) * 4 + fkt) * 128
                                 + ((uint32_t)((rr & 7) ^ fkt) * 16);
                    CP_ASYNC16(sb + m * 8192 + off,
                               srcs[m] + (size_t)rr * KDIM + (kc + 1) * 32 + fc0);
                }
            CP_COMMIT();
            CP_WAIT1();
        } else {
            CP_WAIT0();
        }
        __syncthreads();

        const uint32_t sb = smb + (kc & 1) * 32768;
        const uint32_t aBaseH = sb;
        const uint32_t aBaseL = sb + 8192;
        const uint32_t bBaseH = sb + 16384;
        const uint32_t bBaseL = sb + 24576;

        #pragma unroll
        for (int kt = 0; kt < 2; kt++) {
            uint32_t aF[4][4], bH[4][2], bL[4][2];
            #pragma unroll
            for (int mi = 0; mi < 4; mi++) {
                uint32_t Tm = (uint32_t)(wm * 8 + mi * 2) + (midx & 1);
                uint32_t Tk = (uint32_t)(kt * 2) + (midx >> 1);
                uint32_t addr = aBaseH + (Tm * 4 + Tk) * 128 + ((rsel ^ Tk) * 16);
                LDMATRIX_X4(aF[mi][0], aF[mi][1], aF[mi][2], aF[mi][3], addr);
            }
            #pragma unroll
            for (int nj = 0; nj < 2; nj++) {
                uint32_t Tn = (uint32_t)(wn * 4 + nj * 2) + (midx >> 1);
                uint32_t Tk = (uint32_t)(kt * 2) + (midx & 1);
                uint32_t addr = bBaseH + (Tn * 4 + Tk) * 128 + ((rsel ^ Tk) * 16);
                uint32_t r0, r1, r2, r3;
                LDMATRIX_X4(r0, r1, r2, r3, addr);
                bH[nj * 2][0] = r0; bH[nj * 2][1] = r1;
                bH[nj * 2 + 1][0] = r2; bH[nj * 2 + 1][1] = r3;
            }
            #pragma unroll
            for (int mi = 0; mi < 4; mi++)
                #pragma unroll
                for (int ni = 0; ni < 4; ni++)
                    MMA_BF16(acc[mi][ni], aF[mi], bH[ni]);
            #pragma unroll
            for (int nj = 0; nj < 2; nj++) {
                uint32_t Tn = (uint32_t)(wn * 4 + nj * 2) + (midx >> 1);
                uint32_t Tk = (uint32_t)(kt * 2) + (midx & 1);
                uint32_t addr = bBaseL + (Tn * 4 + Tk) * 128 + ((rsel ^ Tk) * 16);
                uint32_t r0, r1, r2, r3;
                LDMATRIX_X4(r0, r1, r2, r3, addr);
                bL[nj * 2][0] = r0; bL[nj * 2][1] = r1;
                bL[nj * 2 + 1][0] = r2; bL[nj * 2 + 1][1] = r3;
            }
            #pragma unroll
            for (int mi = 0; mi < 4; mi++)
                #pragma unroll
                for (int ni = 0; ni < 4; ni++)
                    MMA_BF16(acc[mi][ni], aF[mi], bL[ni]);
            #pragma unroll
            for (int mi = 0; mi < 4; mi++) {
                uint32_t Tm = (uint32_t)(wm * 8 + mi * 2) + (midx & 1);
                uint32_t Tk = (uint32_t)(kt * 2) + (midx >> 1);
                uint32_t addr = aBaseL + (Tm * 4 + Tk) * 128 + ((rsel ^ Tk) * 16);
                LDMATRIX_X4(aF[mi][0], aF[mi][1], aF[mi][2], aF[mi][3], addr);
            }
            #pragma unroll
            for (int mi = 0; mi < 4; mi++)
                #pragma unroll
                for (int ni = 0; ni < 4; ni++)
                    MMA_BF16(acc[mi][ni], aF[mi], bH[ni]);
        }
        __syncthreads();
    }

    #pragma unroll
    for (int mi = 0; mi < 4; mi++) {
        int row = m0 + wm * 64 + mi * 16 + (lane >> 2);
        #pragma unroll
        for (int ni = 0; ni < 4; ni++) {
            int col = n0 + wn * 32 + ni * 8 + (lane & 3) * 2;
            float b0 = 0.f, b1 = 0.f;
            if (bias) { b0 = bias[col]; b1 = bias[col + 1]; }
            float2 v0, v1;
            v0.x = acc[mi][ni][0] + b0; v0.y = acc[mi][ni][1] + b1;
            v1.x = acc[mi][ni][2] + b0; v1.y = acc[mi][ni][3] + b1;
            *(float2*)&C[(size_t)row * Nout + col] = v0;
            *(float2*)&C[(size_t)(row + 8) * Nout + col] = v1;
        }
    }
}

// ================= tensor-core sliding-window flash attention =================
// grid (L/128, NHEADS, B), 256 threads, smem 196608.
// Q tile 128x128 (hi/lo), K tiles 64x128, V tiles 64x128, double-buffered K/V.
// Output: bf16 hi/lo directly (feeds Wo GEMM).
__global__ void __launch_bounds__(256, 1)
attn_mma_kernel(const __nv_bfloat16* __restrict__ Qh, const __nv_bfloat16* __restrict__ Ql,
                const __nv_bfloat16* __restrict__ Kh, const __nv_bfloat16* __restrict__ Kl,
                const __nv_bfloat16* __restrict__ Vh, const __nv_bfloat16* __restrict__ Vl,
                __nv_bfloat16* __restrict__ Oh, __nv_bfloat16* __restrict__ Ol) {
    extern __shared__ char smem[];
    const uint32_t smb = smem_u32(smem);
    const uint32_t QH_OFF = 0, QL_OFF = 32768, KV_OFF = 65536, KV_STRIDE = 65536;
    const int tid = threadIdx.x, wid = tid >> 5, lane = tid & 31;
    const uint32_t midx = lane >> 3, rsel = lane & 7;
    const int qt = blockIdx.x, h = blockIdx.y, b = blockIdx.z;
    const int qbase = qt * 128;
    const size_t qrow0 = (size_t)(b * L_SEQ + qbase);
    const float scale = 0.08838834764831845f;

    // ---- Q fill (tiled ldmatrix layout, 2 matrices x 2048 chunks) ----
    {
        const __nv_bfloat16* srcQ[2] = {
            Qh + qrow0 * DMODEL + h * HDIM, Ql + qrow0 * DMODEL + h * HDIM };
        #pragma unroll
        for (int m = 0; m < 2; m++) {
            uint32_t base = smb + (m ? QL_OFF : QH_OFF);
            #pragma unroll
            for (int i = 0; i < 8; i++) {
                int cid = tid + i * 256;
                int r = cid >> 4, j = cid & 15;
                uint32_t off = ((uint32_t)(r >> 3) * 16 + j) * 128
                             + ((uint32_t)((r & 7) ^ (j & 7)) * 16);
                CP_ASYNC16(base + off, srcQ[m] + (size_t)r * DMODEL + j * 8);
            }
        }
    }

    int t0 = qbase - (WINDOW - 1);
    if (t0 < 0) t0 = 0;
    t0 >>= 6;
    const int t1 = (qbase + 127) >> 6;

    // ---- K/V tile fill ----
    auto fill_kv = [&](int t, uint32_t sb) {
        const int kbase = t * 64;
        const size_t rowb = (size_t)(b * L_SEQ + kbase);
        const __nv_bfloat16* srcs[4] = {
            Kh + rowb * HDIM, Kl + rowb * HDIM, Vh + rowb * HDIM, Vl + rowb * HDIM };
        #pragma unroll
        for (int m = 0; m < 4; m++) {
            uint32_t base = sb + m * 16384;
            #pragma unroll
            for (int i = 0; i < 4; i++) {
                int cid = tid + i * 256;
                int r = cid >> 4, j = cid & 15;
                uint32_t off;
                if (m < 2)   // K: tiled layout
                    off = ((uint32_t)(r >> 3) * 16 + j) * 128
                        + ((uint32_t)((r & 7) ^ (j & 7)) * 16);
                else         // V: row-major swizzled (256B rows)
                    off = (uint32_t)r * 256 + ((uint32_t)(j ^ (r & 7)) * 16);
                CP_ASYNC16(base + off, srcs[m] + (size_t)r * HDIM + j * 8);
            }
        }
    };
    fill_kv(t0, smb + KV_OFF);
    CP_COMMIT();   // group: Q + tile t0

    float acc[16][4];
    #pragma unroll
    for (int i = 0; i < 16; i++)
        #pragma unroll
        for (int c = 0; c < 4; c++) acc[i][c] = 0.0f;
    float m0r = -1e30f, m1r = -1e30f, l0r = 0.0f, l1r = 0.0f;

    const int gR0 = qbase + wid * 16 + (lane >> 2);   // gR1 = gR0 + 8
    const uint32_t sQh = smb + QH_OFF, sQl = smb + QL_OFF;

    for (int t = t0; t <= t1; t++) {
        if (t < t1) {
            fill_kv(t + 1, smb + KV_OFF + ((t + 1) & 1) * KV_STRIDE);
            CP_COMMIT();
            CP_WAIT1();
        } else {
            CP_WAIT0();
        }
        __syncthreads();

        const uint32_t sKV = smb + KV_OFF + (t & 1) * KV_STRIDE;
        const uint32_t sKh = sKV, sKl = sKV + 16384;
        const uint32_t sVh = sKV + 32768, sVl = sKV + 49152;
        const int kbase = t * 64;

        // ---- scores S = Q K^T (3-pass hi/lo) ----
        float sc[8][4];
        #pragma unroll
        for (int i = 0; i < 8; i++)
            #pragma unroll
            for (int c = 0; c < 4; c++) sc[i][c] = 0.0f;

        const uint32_t TmA = (uint32_t)(wid * 2) + (midx & 1);
        #pragma unroll
        for (int ks = 0; ks < 8; ks++) {
            uint32_t aH[4], aL[4], bH[8][2], bL[8][2];
            uint32_t TkA = (uint32_t)(ks * 2) + (midx >> 1);
            uint32_t offA = (TmA * 16 + TkA) * 128 + ((rsel ^ (TkA & 7)) * 16);
            LDMATRIX_X4(aH[0], aH[1], aH[2], aH[3], sQh + offA);
            LDMATRIX_X4(aL[0], aL[1], aL[2], aL[3], sQl + offA);
            uint32_t TkB = (uint32_t)(ks * 2) + (midx & 1);
            #pragma unroll
            for (int nj = 0; nj < 4; nj++) {
                uint32_t Tn = (uint32_t)(nj * 2) + (midx >> 1);
                uint32_t off = (Tn * 16 + TkB) * 128 + ((rsel ^ (TkB & 7)) * 16);
                uint32_t r0, r1, r2, r3;
                LDMATRIX_X4(r0, r1, r2, r3, sKh + off);
                bH[nj * 2][0] = r0; bH[nj * 2][1] = r1;
                bH[nj * 2 + 1][0] = r2; bH[nj * 2 + 1][1] = r3;
                LDMATRIX_X4(r0, r1, r2, r3, sKl + off);
                bL[nj * 2][0] = r0; bL[nj * 2][1] = r1;
                bL[nj * 2 + 1][0] = r2; bL[nj * 2 + 1][1] = r3;
            }
            #pragma unroll
            for (int nf = 0; nf < 8; nf++) MMA_BF16(sc[nf], aH, bH[nf]);
            #pragma unroll
            for (int nf = 0; nf < 8; nf++) MMA_BF16(sc[nf], aH, bL[nf]);
            #pragma unroll
            for (int nf = 0; nf < 8; nf++) MMA_BF16(sc[nf], aL, bH[nf]);
        }

        // ---- mask + online softmax ----
        float mx0 = -1e30f, mx1 = -1e30f;
        #pragma unroll
        for (int nf = 0; nf < 8; nf++) {
            int col = kbase + nf * 8 + (lane & 3) * 2;
            int d00 = gR0 - col, d01 = d00 - 1;
            int d10 = gR0 + 8 - col, d11 = d10 - 1;
            sc[nf][0] = sc[nf][0] * scale + ((d00 >= 0 && d00 < WINDOW) ? 0.f : -1e9f);
            sc[nf][1] = sc[nf][1] * scale + ((d01 >= 0 && d01 < WINDOW) ? 0.f : -1e9f);
            sc[nf][2] = sc[nf][2] * scale + ((d10 >= 0 && d10 < WINDOW) ? 0.f : -1e9f);
            sc[nf][3] = sc[nf][3] * scale + ((d11 >= 0 && d11 < WINDOW) ? 0.f : -1e9f);
            mx0 = fmaxf(mx0, fmaxf(sc[nf][0], sc[nf][1]));
            mx1 = fmaxf(mx1, fmaxf(sc[nf][2], sc[nf][3]));
        }
        mx0 = fmaxf(mx0, __shfl_xor_sync(0xffffffffu, mx0, 1));
        mx0 = fmaxf(mx0, __shfl_xor_sync(0xffffffffu, mx0, 2));
        mx1 = fmaxf(mx1, __shfl_xor_sync(0xffffffffu, mx1, 1));
        mx1 = fmaxf(mx1, __shfl_xor_sync(0xffffffffu, mx1, 2));
        float mn0 = fmaxf(m0r, mx0), mn1 = fmaxf(m1r, mx1);
        float corr0 = __expf(m0r - mn0), corr1 = __expf(m1r - mn1);
        m0r = mn0; m1r = mn1;
        float rs0 = 0.f, rs1 = 0.f;
        #pragma unroll
        for (int nf = 0; nf < 8; nf++) {
            sc[nf][0] = __expf(sc[nf][0] - mn0);
            sc[nf][1] = __expf(sc[nf][1] - mn0);
            sc[nf][2] = __expf(sc[nf][2] - mn1);
            sc[nf][3] = __expf(sc[nf][3] - mn1);
            rs0 += sc[nf][0] + sc[nf][1];
            rs1 += sc[nf][2] + sc[nf][3];
        }
        rs0 += __shfl_xor_sync(0xffffffffu, rs0, 1);
        rs0 += __shfl_xor_sync(0xffffffffu, rs0, 2);
        rs1 += __shfl_xor_sync(0xffffffffu, rs1, 1);
        rs1 += __shfl_xor_sync(0xffffffffu, rs1, 2);
        l0r = l0r * corr0 + rs0;
        l1r = l1r * corr1 + rs1;
        #pragma unroll
        for (int nf = 0; nf < 16; nf++) {
            acc[nf][0] *= corr0; acc[nf][1] *= corr0;
            acc[nf][2] *= corr1; acc[nf][3] *= corr1;
        }

        // ---- P -> bf16 hi/lo A-frags (no shuffles) ----
        uint32_t aPh[4][4], aPl[4][4];
        #pragma unroll
        for (int kt2 = 0; kt2 < 4; kt2++) {
            #pragma unroll
            for (int half = 0; half < 2; half++) {
                int nf = kt2 * 2 + half;
                __nv_bfloat162 h01 = __floats2bfloat162_rn(sc[nf][0], sc[nf][1]);
                __nv_bfloat162 h23 = __floats2bfloat162_rn(sc[nf][2], sc[nf][3]);
                float e0 = sc[nf][0] - __low2float(h01);
                float e1 = sc[nf][1] - __high2float(h01);
                float e2 = sc[nf][2] - __low2float(h23);
                float e3 = sc[nf][3] - __high2float(h23);
                __nv_bfloat162 l01 = __floats2bfloat162_rn(e0, e1);
                __nv_bfloat162 l23 = __floats2bfloat162_rn(e2, e3);
                aPh[kt2][half * 2 + 0] = *(uint32_t*)&h01;
                aPh[kt2][half * 2 + 1] = *(uint32_t*)&h23;
                aPl[kt2][half * 2 + 0] = *(uint32_t*)&l01;
                aPl[kt2][half * 2 + 1] = *(uint32_t*)&l23;
            }
        }

        // ---- PV (3-pass: Ph*Vh + Pl*Vh + Ph*Vl) ----
        #pragma unroll
        for (int kt2 = 0; kt2 < 4; kt2++) {
            uint32_t bb[16][2];
            // trans-ldmatrix address: lane group g
            uint32_t krow = (uint32_t)(kt2 * 16) + ((midx & 1) * 8) + rsel;
            #pragma unroll
            for (int nj = 0; nj < 8; nj++) {
                uint32_t j = (uint32_t)(nj * 2) + (midx >> 1);
                uint32_t off = krow * 256 + ((j ^ rsel) * 16);
                uint32_t r0, r1, r2, r3;
                LDMATRIX_X4_T(r0, r1, r2, r3, sVh + off);
                bb[nj * 2][0] = r0; bb[nj * 2][1] = r1;
                bb[nj * 2 + 1][0] = r2; bb[nj * 2 + 1][1] = r3;
            }
            #pragma unroll
            for (int nf = 0; nf < 16; nf++) MMA_BF16(acc[nf], aPh[kt2], bb[nf]);
            #pragma unroll
            for (int nf = 0; nf < 16; nf++) MMA_BF16(acc[nf], aPl[kt2], bb[nf]);
            #pragma unroll
            for (int nj = 0; nj < 8; nj++) {
                uint32_t j = (uint32_t)(nj * 2) + (midx >> 1);
                uint32_t off = krow * 256 + ((j ^ rsel) * 16);
                uint32_t r0, r1, r2, r3;
                LDMATRIX_X4_T(r0, r1, r2, r3, sVl + off);
                bb[nj * 2][0] = r0; bb[nj * 2][1] = r1;
                bb[nj * 2 + 1][0] = r2; bb[nj * 2 + 1][1] = r3;
            }
            #pragma unroll
            for (int nf = 0; nf < 16; nf++) MMA_BF16(acc[nf], aPh[kt2], bb[nf]);
        }
        __syncthreads();   // done with this stage's smem before it is refilled
    }

    // ---- epilogue: normalize, split to bf16 hi/lo ----
    float inv0 = 1.0f / l0r, inv1 = 1.0f / l1r;
    size_t row0 = qrow0 + wid * 16 + (lane >> 2);
    size_t row1 = row0 + 8;
    #pragma unroll
    for (int nf = 0; nf < 16; nf++) {
        int col = h * HDIM + nf * 8 + (lane & 3) * 2;
        float o0 = acc[nf][0] * inv0, o1 = acc[nf][1] * inv0;
        float o2 = acc[nf][2] * inv1, o3 = acc[nf][3] * inv1;
        __nv_bfloat162 h01 = __floats2bfloat162_rn(o0, o1);
        __nv_bfloat162 h23 = __floats2bfloat162_rn(o2, o3);
        __nv_bfloat162 l01 = __floats2bfloat162_rn(o0 - __low2float(h01), o1 - __high2float(h01));
        __nv_bfloat162 l23 = __floats2bfloat162_rn(o2 - __low2float(h23), o3 - __high2float(h23));
        *(uint32_t*)&Oh[row0 * DMODEL + col] = *(uint32_t*)&h01;
        *(uint32_t*)&Oh[row1 * DMODEL + col] = *(uint32_t*)&h23;
        *(uint32_t*)&Ol[row0 * DMODEL + col] = *(uint32_t*)&l01;
        *(uint32_t*)&Ol[row1 * DMODEL + col] = *(uint32_t*)&l23;
    }
}

// ================= launch =================
extern "C" void kernel_launch(void* const* d_in, const int* in_sizes, int n_in,
                              void* d_out, int out_size) {
    const float* x  = (const float*)d_in[0];
    const float* Wq = (const float*)d_in[1];
    const float* Wk = (const float*)d_in[2];
    const float* Wv = (const float*)d_in[3];
    const float* Wo = (const float*)d_in[4];
    const float* bo = (const float*)d_in[5];
    float* out = (float*)d_out;

    float *q, *kv;
    __nv_bfloat16 *xh, *xl, *qh, *ql, *kh, *kl, *vh, *vl, *ath, *atl;
    __nv_bfloat16 *wqh, *wql, *woh, *wol, *wkvh, *wkvl;
    cudaGetSymbolAddress((void**)&q,   g_q);
    cudaGetSymbolAddress((void**)&kv,  g_kv);
    cudaGetSymbolAddress((void**)&xh,  g_xh);
    cudaGetSymbolAddress((void**)&xl,  g_xl);
    cudaGetSymbolAddress((void**)&qh,  g_qh);
    cudaGetSymbolAddress((void**)&ql,  g_ql);
    cudaGetSymbolAddress((void**)&kh,  g_kh);
    cudaGetSymbolAddress((void**)&kl,  g_kl);
    cudaGetSymbolAddress((void**)&vh,  g_vh);
    cudaGetSymbolAddress((void**)&vl,  g_vl);
    cudaGetSymbolAddress((void**)&ath, g_ath);
    cudaGetSymbolAddress((void**)&atl, g_atl);
    cudaGetSymbolAddress((void**)&wqh, g_wqt_h);
    cudaGetSymbolAddress((void**)&wql, g_wqt_l);
    cudaGetSymbolAddress((void**)&woh, g_wot_h);
    cudaGetSymbolAddress((void**)&wol, g_wot_l);
    cudaGetSymbolAddress((void**)&wkvh, g_wkvt_h);
    cudaGetSymbolAddress((void**)&wkvl, g_wkvt_l);

    const int GEMM_SMEM = 65536;
    cudaFuncSetAttribute(gemm_bf16_kernel,
                         cudaFuncAttributeMaxDynamicSharedMemorySize, GEMM_SMEM);
    const int ATTN_SMEM = 196608;
    cudaFuncSetAttribute(attn_mma_kernel,
                         cudaFuncAttributeMaxDynamicSharedMemorySize, ATTN_SMEM);

    // prep
    rope_table_kernel<<<(L_SEQ * 32 + 255) / 256, 256>>>();
    split_kernel<<<(BROWS * DMODEL) / 256, 256>>>(x, xh, xl, BROWS * DMODEL);
    dim3 tb(32, 8);
    tsplit_kernel<<<dim3(DMODEL / 32, KDIM / 32), tb>>>(Wq, wqh, wql, DMODEL, 0);
    tsplit_kernel<<<dim3(HDIM / 32, KDIM / 32), tb>>>(Wk, wkvh, wkvl, HDIM, 0);
    tsplit_kernel<<<dim3(HDIM / 32, KDIM / 32), tb>>>(Wv, wkvh, wkvl, HDIM, 128);
    tsplit_kernel<<<dim3(DMODEL / 32, KDIM / 32), tb>>>(Wo, woh, wol, DMODEL, 0);

    // fused Q + KV projection (one launch, kv blocks ride along)
    gemm_bf16_kernel<<<dim3(18, BROWS / 128), 256, GEMM_SMEM>>>(
        xh, xl, wqh, wql, nullptr, q, DMODEL, 16, wkvh, wkvl, kv, 256);

    // RoPE + hi/lo splits
    rope_split_q_kernel<<<(BROWS * NHEADS * 64) / 256, 256>>>();
    rope_split_kv_kernel<<<(BROWS * 64) / 256, 256>>>();

    // tensor-core attention -> bf16 hi/lo
    dim3 ga(L_SEQ / 128, NHEADS, 2);
    attn_mma_kernel<<<ga, 256, ATTN_SMEM>>>(qh, ql, kh, kl, vh, vl, ath, atl);

    // output projection + bias
    gemm_bf16_kernel<<<dim3(16, BROWS / 128), 256, GEMM_SMEM>>>(
        ath, atl, woh, wol, bo, out, DMODEL, 16, woh, wol, out, DMODEL);
}

// round 5
// speedup vs baseline: 2.7096x; 1.0435x over previous
#include <cuda_runtime.h>
#include <cuda_bf16.h>
#include <math.h>
#include <stdint.h>

#define L_SEQ   2048
#define DMODEL  2048
#define NHEADS  16
#define HDIM    128
#define WINDOW  512
#define BROWS   4096   // B * L
#define KDIM    2048

typedef __nv_bfloat16 bf16;

// ================= scratch =================
__device__ float g_cs[L_SEQ * 64];          // (cos,sin) interleaved per (pos, c<32)
__device__ bf16 g_xh[BROWS * DMODEL];
__device__ bf16 g_xl[BROWS * DMODEL];
__device__ bf16 g_qh[BROWS * DMODEL];
__device__ bf16 g_ql[BROWS * DMODEL];
__device__ bf16 g_kh[BROWS * HDIM];
__device__ bf16 g_kl[BROWS * HDIM];
__device__ bf16 g_vh[BROWS * HDIM];
__device__ bf16 g_vl[BROWS * HDIM];
__device__ bf16 g_ath[BROWS * DMODEL];
__device__ bf16 g_atl[BROWS * DMODEL];
__device__ bf16 g_wqt_h[DMODEL * KDIM];
__device__ bf16 g_wqt_l[DMODEL * KDIM];
__device__ bf16 g_wot_h[DMODEL * KDIM];
__device__ bf16 g_wot_l[DMODEL * KDIM];
__device__ bf16 g_wkvt_h[256 * KDIM];
__device__ bf16 g_wkvt_l[256 * KDIM];

// ================= helpers =================
__device__ __forceinline__ uint32_t smem_u32(const void* p) {
    uint32_t a;
    asm("{ .reg .u64 t; cvta.to.shared.u64 t, %1; cvt.u32.u64 %0, t; }" : "=r"(a) : "l"(p));
    return a;
}
#define CP_ASYNC16(saddr, gptr) \
    asm volatile("cp.async.cg.shared.global [%0], [%1], 16;" :: "r"(saddr), "l"(gptr))
#define CP_COMMIT()  asm volatile("cp.async.commit_group;" ::: "memory")
#define CP_WAIT0()   asm volatile("cp.async.wait_group 0;" ::: "memory")
#define CP_WAIT1()   asm volatile("cp.async.wait_group 1;" ::: "memory")

#define LDMATRIX_X4(r0, r1, r2, r3, addr) \
    asm volatile("ldmatrix.sync.aligned.m8n8.x4.shared.b16 {%0,%1,%2,%3}, [%4];" \
        : "=r"(r0), "=r"(r1), "=r"(r2), "=r"(r3) : "r"(addr))

#define LDMATRIX_X4_T(r0, r1, r2, r3, addr) \
    asm volatile("ldmatrix.sync.aligned.m8n8.x4.trans.shared.b16 {%0,%1,%2,%3}, [%4];" \
        : "=r"(r0), "=r"(r1), "=r"(r2), "=r"(r3) : "r"(addr))

#define MMA_BF16(c, a, b) \
    asm volatile("mma.sync.aligned.m16n8k16.row.col.f32.bf16.bf16.f32 " \
        "{%0,%1,%2,%3}, {%4,%5,%6,%7}, {%8,%9}, {%0,%1,%2,%3};" \
        : "+f"((c)[0]), "+f"((c)[1]), "+f"((c)[2]), "+f"((c)[3]) \
        : "r"((a)[0]), "r"((a)[1]), "r"((a)[2]), "r"((a)[3]), "r"((b)[0]), "r"((b)[1]))

__device__ __forceinline__ uint32_t pack_split(float a, float b, uint32_t& lo) {
    __nv_bfloat162 h = __floats2bfloat162_rn(a, b);
    __nv_bfloat162 l = __floats2bfloat162_rn(a - __low2float(h), b - __high2float(h));
    lo = *(uint32_t*)&l;
    return *(uint32_t*)&h;
}

// ================= prep kernels =================
__global__ void rope_table_kernel() {
    int idx = blockIdx.x * blockDim.x + threadIdx.x;
    if (idx >= L_SEQ * 32) return;
    int pos = idx >> 5;
    int i = idx & 31;
    double inv = exp(-log(10000.0) * ((double)(2 * i) / 64.0));
    double th = (double)pos * inv;
    g_cs[pos * 64 + i * 2 + 0] = (float)cos(th);
    g_cs[pos * 64 + i * 2 + 1] = (float)sin(th);
}

__global__ void split_kernel(const float* __restrict__ in,
                             bf16* __restrict__ hi, bf16* __restrict__ lo, int n) {
    int idx = blockIdx.x * blockDim.x + threadIdx.x;
    if (idx >= n) return;
    float v = in[idx];
    bf16 h = __float2bfloat16(v);
    hi[idx] = h;
    lo[idx] = __float2bfloat16(v - __bfloat162float(h));
}

// W [K][N] fp32 -> Th/Tl [ro+N][KDIM] bf16 (transposed + split)
__global__ void tsplit_kernel(const float* __restrict__ W,
                              bf16* __restrict__ Th, bf16* __restrict__ Tl,
                              int N, int ro) {
    __shared__ float tile[32][33];
    int n0 = blockIdx.x * 32, k0 = blockIdx.y * 32;
    int tx = threadIdx.x, ty = threadIdx.y;
    #pragma unroll
    for (int i = ty; i < 32; i += 8)
        tile[i][tx] = W[(size_t)(k0 + i) * N + n0 + tx];
    __syncthreads();
    #pragma unroll
    for (int i = ty; i < 32; i += 8) {
        float v = tile[tx][i];
        bf16 h = __float2bfloat16(v);
        size_t o = (size_t)(ro + n0 + i) * KDIM + k0 + tx;
        Th[o] = h;
        Tl[o] = __float2bfloat16(v - __bfloat162float(h));
    }
}

// fused Wk+Wv (z = 0 -> K rows 0..127, z = 1 -> V rows 128..255)
__global__ void tsplit_kv_kernel(const float* __restrict__ Wk,
                                 const float* __restrict__ Wv) {
    __shared__ float tile[32][33];
    const float* W = blockIdx.z ? Wv : Wk;
    int ro = blockIdx.z ? 128 : 0;
    int n0 = blockIdx.x * 32, k0 = blockIdx.y * 32;
    int tx = threadIdx.x, ty = threadIdx.y;
    #pragma unroll
    for (int i = ty; i < 32; i += 8)
        tile[i][tx] = W[(size_t)(k0 + i) * HDIM + n0 + tx];
    __syncthreads();
    #pragma unroll
    for (int i = ty; i < 32; i += 8) {
        float v = tile[tx][i];
        bf16 h = __float2bfloat16(v);
        size_t o = (size_t)(ro + n0 + i) * KDIM + k0 + tx;
        g_wkvt_h[o] = h;
        g_wkvt_l[o] = __float2bfloat16(v - __bfloat162float(h));
    }
}

// ================= mma.sync bf16 GEMM, 3-stage pipeline =================
// QKV=true : grid (18, 32): blocks 0..15 Q (rope+split), 16 K (rope+split), 17 V (split)
// QKV=false: grid (16, 32): O projection, fp32 + bias -> Cout
template <bool QKV>
__global__ void __launch_bounds__(256, 2)
gemm_kernel(const float* __restrict__ bias, float* __restrict__ Cout) {
    extern __shared__ char smem[];
    const uint32_t smb = smem_u32(smem);
    const int tid = threadIdx.x;
    const int wid = tid >> 5;
    const int lane = tid & 31;
    const int wm = wid >> 1;          // 0..3 (32 rows)
    const int wn = wid & 1;           // 0..1 (64 cols)
    const uint32_t midx = lane >> 3;
    const uint32_t rsel = lane & 7;

    const int m0 = blockIdx.y * 128;
    const bf16* Ah = QKV ? g_xh : g_ath;
    const bf16* Al = QKV ? g_xl : g_atl;
    const bf16* Bh;
    const bf16* Bl;
    int n0;
    bf16 *OutH = nullptr, *OutL = nullptr;
    int strideO = 0, colBase = 0;
    bool do_rope = false;
    if (QKV) {
        if ((int)blockIdx.x < 16) {
            Bh = g_wqt_h; Bl = g_wqt_l; n0 = blockIdx.x * 128;
            OutH = g_qh; OutL = g_ql; strideO = DMODEL; colBase = n0; do_rope = true;
        } else if (blockIdx.x == 16) {
            Bh = g_wkvt_h; Bl = g_wkvt_l; n0 = 0;
            OutH = g_kh; OutL = g_kl; strideO = HDIM; colBase = 0; do_rope = true;
        } else {
            Bh = g_wkvt_h; Bl = g_wkvt_l; n0 = 128;
            OutH = g_vh; OutL = g_vl; strideO = HDIM; colBase = 0; do_rope = false;
        }
    } else {
        Bh = g_wot_h; Bl = g_wot_l; n0 = blockIdx.x * 128;
    }

    const bf16* srcs[4] = {
        Ah + (size_t)m0 * KDIM, Al + (size_t)m0 * KDIM,
        Bh + (size_t)n0 * KDIM, Bl + (size_t)n0 * KDIM };

    const int fr = tid >> 2;
    const uint32_t fkt = (uint32_t)(tid & 3);
    const int fc0 = (tid & 3) * 8;

    auto fill = [&](int kc, uint32_t sbase) {
        #pragma unroll
        for (int m = 0; m < 4; m++)
            #pragma unroll
            for (int half = 0; half < 2; half++) {
                int rr = fr + half * 64;
                uint32_t off = ((uint32_t)(rr >> 3) * 4 + fkt) * 128
                             + ((uint32_t)((rr & 7) ^ fkt) * 16);
                CP_ASYNC16(sbase + m * 8192 + off,
                           srcs[m] + (size_t)rr * KDIM + kc * 32 + fc0);
            }
    };

    float acc[2][8][4];
    #pragma unroll
    for (int i = 0; i < 2; i++)
        #pragma unroll
        for (int j = 0; j < 8; j++)
            #pragma unroll
            for (int c = 0; c < 4; c++) acc[i][j][c] = 0.0f;

    fill(0, smb);          CP_COMMIT();
    fill(1, smb + 32768);  CP_COMMIT();

    const int NK = KDIM / 32;
    for (int kc = 0; kc < NK; kc++) {
        if (kc + 1 < NK) CP_WAIT1(); else CP_WAIT0();
        __syncthreads();
        if (kc + 2 < NK) {
            fill(kc + 2, smb + ((kc + 2) % 3) * 32768);
            CP_COMMIT();
        }

        const uint32_t sb = smb + (kc % 3) * 32768;
        const uint32_t aBaseH = sb;
        const uint32_t aBaseL = sb + 8192;
        const uint32_t bBaseH = sb + 16384;
        const uint32_t bBaseL = sb + 24576;

        #pragma unroll
        for (int kt = 0; kt < 2; kt++) {
            uint32_t aH[2][4], aL[2][4], bF[8][2];
            const uint32_t TkA = (uint32_t)(kt * 2) + (midx >> 1);
            const uint32_t TkB = (uint32_t)(kt * 2) + (midx & 1);
            // A hi
            #pragma unroll
            for (int mi = 0; mi < 2; mi++) {
                uint32_t Tm = (uint32_t)(wm * 4 + mi * 2) + (midx & 1);
                uint32_t addr = aBaseH + (Tm * 4 + TkA) * 128 + ((rsel ^ TkA) * 16);
                LDMATRIX_X4(aH[mi][0], aH[mi][1], aH[mi][2], aH[mi][3], addr);
            }
            // B hi
            #pragma unroll
            for (int nj = 0; nj < 4; nj++) {
                uint32_t Tn = (uint32_t)(wn * 8 + nj * 2) + (midx >> 1);
                uint32_t addr = bBaseH + (Tn * 4 + TkB) * 128 + ((rsel ^ TkB) * 16);
                uint32_t r0, r1, r2, r3;
                LDMATRIX_X4(r0, r1, r2, r3, addr);
                bF[nj * 2][0] = r0; bF[nj * 2][1] = r1;
                bF[nj * 2 + 1][0] = r2; bF[nj * 2 + 1][1] = r3;
            }
            // pass hh
            #pragma unroll
            for (int mi = 0; mi < 2; mi++)
                #pragma unroll
                for (int nf = 0; nf < 8; nf++)
                    MMA_BF16(acc[mi][nf], aH[mi], bF[nf]);
            // A lo
            #pragma unroll
            for (int mi = 0; mi < 2; mi++) {
                uint32_t Tm = (uint32_t)(wm * 4 + mi * 2) + (midx & 1);
                uint32_t addr = aBaseL + (Tm * 4 + TkA) * 128 + ((rsel ^ TkA) * 16);
                LDMATRIX_X4(aL[mi][0], aL[mi][1], aL[mi][2], aL[mi][3], addr);
            }
            // pass lh
            #pragma unroll
            for (int mi = 0; mi < 2; mi++)
                #pragma unroll
                for (int nf = 0; nf < 8; nf++)
                    MMA_BF16(acc[mi][nf], aL[mi], bF[nf]);
            // B lo (reuse bF registers)
            #pragma unroll
            for (int nj = 0; nj < 4; nj++) {
                uint32_t Tn = (uint32_t)(wn * 8 + nj * 2) + (midx >> 1);
                uint32_t addr = bBaseL + (Tn * 4 + TkB) * 128 + ((rsel ^ TkB) * 16);
                uint32_t r0, r1, r2, r3;
                LDMATRIX_X4(r0, r1, r2, r3, addr);
                bF[nj * 2][0] = r0; bF[nj * 2][1] = r1;
                bF[nj * 2 + 1][0] = r2; bF[nj * 2 + 1][1] = r3;
            }
            // pass hl
            #pragma unroll
            for (int mi = 0; mi < 2; mi++)
                #pragma unroll
                for (int nf = 0; nf < 8; nf++)
                    MMA_BF16(acc[mi][nf], aH[mi], bF[nf]);
        }
        __syncthreads();
    }

    // ================= epilogue =================
    if (!QKV) {
        #pragma unroll
        for (int mi = 0; mi < 2; mi++) {
            int row = m0 + wm * 32 + mi * 16 + (lane >> 2);
            #pragma unroll
            for (int nf = 0; nf < 8; nf++) {
                int col = n0 + wn * 64 + nf * 8 + (lane & 3) * 2;
                float b0 = bias[col], b1 = bias[col + 1];
                float2 v0, v1;
                v0.x = acc[mi][nf][0] + b0; v0.y = acc[mi][nf][1] + b1;
                v1.x = acc[mi][nf][2] + b0; v1.y = acc[mi][nf][3] + b1;
                *(float2*)&Cout[(size_t)row * DMODEL + col] = v0;
                *(float2*)&Cout[(size_t)(row + 8) * DMODEL + col] = v1;
            }
        }
        return;
    }

    // rope (in registers) for Q and K blocks; wn==0 holds cols 0..63 (pairs c, c+32)
    if (do_rope && wn == 0) {
        #pragma unroll
        for (int mi = 0; mi < 2; mi++) {
            int r0 = m0 + wm * 32 + mi * 16 + (lane >> 2);
            int pos0 = r0 & (L_SEQ - 1);
            int pos1 = (r0 + 8) & (L_SEQ - 1);
            #pragma unroll
            for (int nf = 0; nf < 4; nf++) {
                int c = nf * 8 + (lane & 3) * 2;   // 0..30
                float2 csA0 = *(float2*)&g_cs[pos0 * 64 + c * 2];
                float2 csB0 = *(float2*)&g_cs[pos0 * 64 + c * 2 + 2];
                float2 csA1 = *(float2*)&g_cs[pos1 * 64 + c * 2];
                float2 csB1 = *(float2*)&g_cs[pos1 * 64 + c * 2 + 2];
                float x1, x2;
                x1 = acc[mi][nf][0]; x2 = acc[mi][nf + 4][0];
                acc[mi][nf][0]     = x1 * csA0.x - x2 * csA0.y;
                acc[mi][nf + 4][0] = x1 * csA0.y + x2 * csA0.x;
                x1 = acc[mi][nf][1]; x2 = acc[mi][nf + 4][1];
                acc[mi][nf][1]     = x1 * csB0.x - x2 * csB0.y;
                acc[mi][nf + 4][1] = x1 * csB0.y + x2 * csB0.x;
                x1 = acc[mi][nf][2]; x2 = acc[mi][nf + 4][2];
                acc[mi][nf][2]     = x1 * csA1.x - x2 * csA1.y;
                acc[mi][nf + 4][2] = x1 * csA1.y + x2 * csA1.x;
                x1 = acc[mi][nf][3]; x2 = acc[mi][nf + 4][3];
                acc[mi][nf][3]     = x1 * csB1.x - x2 * csB1.y;
                acc[mi][nf + 4][3] = x1 * csB1.y + x2 * csB1.x;
            }
        }
    }

    // split-store bf16 hi/lo
    #pragma unroll
    for (int mi = 0; mi < 2; mi++) {
        int row = m0 + wm * 32 + mi * 16 + (lane >> 2);
        #pragma unroll
        for (int nf = 0; nf < 8; nf++) {
            int cl = colBase + wn * 64 + nf * 8 + (lane & 3) * 2;
            uint32_t lo, hi;
            hi = pack_split(acc[mi][nf][0], acc[mi][nf][1], lo);
            *(uint32_t*)&OutH[(size_t)row * strideO + cl] = hi;
            *(uint32_t*)&OutL[(size_t)row * strideO + cl] = lo;
            hi = pack_split(acc[mi][nf][2], acc[mi][nf][3], lo);
            *(uint32_t*)&OutH[(size_t)(row + 8) * strideO + cl] = hi;
            *(uint32_t*)&OutL[(size_t)(row + 8) * strideO + cl] = lo;
        }
    }
}

// ================= tensor-core sliding-window flash attention =================
__global__ void __launch_bounds__(256, 1)
attn_mma_kernel(const bf16* __restrict__ Qh, const bf16* __restrict__ Ql,
                const bf16* __restrict__ Kh, const bf16* __restrict__ Kl,
                const bf16* __restrict__ Vh, const bf16* __restrict__ Vl,
                bf16* __restrict__ Oh, bf16* __restrict__ Ol) {
    extern __shared__ char smem[];
    const uint32_t smb = smem_u32(smem);
    const uint32_t QH_OFF = 0, QL_OFF = 32768, KV_OFF = 65536, KV_STRIDE = 65536;
    const int tid = threadIdx.x, wid = tid >> 5, lane = tid & 31;
    const uint32_t midx = lane >> 3, rsel = lane & 7;
    const int qt = blockIdx.x, h = blockIdx.y, b = blockIdx.z;
    const int qbase = qt * 128;
    const size_t qrow0 = (size_t)(b * L_SEQ + qbase);
    const float scale = 0.08838834764831845f;

    {
        const bf16* srcQ[2] = {
            Qh + qrow0 * DMODEL + h * HDIM, Ql + qrow0 * DMODEL + h * HDIM };
        #pragma unroll
        for (int m = 0; m < 2; m++) {
            uint32_t base = smb + (m ? QL_OFF : QH_OFF);
            #pragma unroll
            for (int i = 0; i < 8; i++) {
                int cid = tid + i * 256;
                int r = cid >> 4, j = cid & 15;
                uint32_t off = ((uint32_t)(r >> 3) * 16 + j) * 128
                             + ((uint32_t)((r & 7) ^ (j & 7)) * 16);
                CP_ASYNC16(base + off, srcQ[m] + (size_t)r * DMODEL + j * 8);
            }
        }
    }

    int t0 = qbase - (WINDOW - 1);
    if (t0 < 0) t0 = 0;
    t0 >>= 6;
    const int t1 = (qbase + 127) >> 6;

    auto fill_kv = [&](int t, uint32_t sb) {
        const int kbase = t * 64;
        const size_t rowb = (size_t)(b * L_SEQ + kbase);
        const bf16* srcs[4] = {
            Kh + rowb * HDIM, Kl + rowb * HDIM, Vh + rowb * HDIM, Vl + rowb * HDIM };
        #pragma unroll
        for (int m = 0; m < 4; m++) {
            uint32_t base = sb + m * 16384;
            #pragma unroll
            for (int i = 0; i < 4; i++) {
                int cid = tid + i * 256;
                int r = cid >> 4, j = cid & 15;
                uint32_t off;
                if (m < 2)
                    off = ((uint32_t)(r >> 3) * 16 + j) * 128
                        + ((uint32_t)((r & 7) ^ (j & 7)) * 16);
                else
                    off = (uint32_t)r * 256 + ((uint32_t)(j ^ (r & 7)) * 16);
                CP_ASYNC16(base + off, srcs[m] + (size_t)r * HDIM + j * 8);
            }
        }
    };
    fill_kv(t0, smb + KV_OFF);
    CP_COMMIT();

    float acc[16][4];
    #pragma unroll
    for (int i = 0; i < 16; i++)
        #pragma unroll
        for (int c = 0; c < 4; c++) acc[i][c] = 0.0f;
    float m0r = -1e30f, m1r = -1e30f, l0r = 0.0f, l1r = 0.0f;

    const int gR0 = qbase + wid * 16 + (lane >> 2);
    const uint32_t sQh = smb + QH_OFF, sQl = smb + QL_OFF;

    for (int t = t0; t <= t1; t++) {
        if (t < t1) {
            fill_kv(t + 1, smb + KV_OFF + ((t + 1) & 1) * KV_STRIDE);
            CP_COMMIT();
            CP_WAIT1();
        } else {
            CP_WAIT0();
        }
        __syncthreads();

        const uint32_t sKV = smb + KV_OFF + (t & 1) * KV_STRIDE;
        const uint32_t sKh = sKV, sKl = sKV + 16384;
        const uint32_t sVh = sKV + 32768, sVl = sKV + 49152;
        const int kbase = t * 64;

        float sc[8][4];
        #pragma unroll
        for (int i = 0; i < 8; i++)
            #pragma unroll
            for (int c = 0; c < 4; c++) sc[i][c] = 0.0f;

        const uint32_t TmA = (uint32_t)(wid * 2) + (midx & 1);
        #pragma unroll
        for (int ks = 0; ks < 8; ks++) {
            uint32_t aH[4], aL[4], bH[8][2], bL[8][2];
            uint32_t TkA = (uint32_t)(ks * 2) + (midx >> 1);
            uint32_t offA = (TmA * 16 + TkA) * 128 + ((rsel ^ (TkA & 7)) * 16);
            LDMATRIX_X4(aH[0], aH[1], aH[2], aH[3], sQh + offA);
            LDMATRIX_X4(aL[0], aL[1], aL[2], aL[3], sQl + offA);
            uint32_t TkB = (uint32_t)(ks * 2) + (midx & 1);
            #pragma unroll
            for (int nj = 0; nj < 4; nj++) {
                uint32_t Tn = (uint32_t)(nj * 2) + (midx >> 1);
                uint32_t off = (Tn * 16 + TkB) * 128 + ((rsel ^ (TkB & 7)) * 16);
                uint32_t r0, r1, r2, r3;
                LDMATRIX_X4(r0, r1, r2, r3, sKh + off);
                bH[nj * 2][0] = r0; bH[nj * 2][1] = r1;
                bH[nj * 2 + 1][0] = r2; bH[nj * 2 + 1][1] = r3;
                LDMATRIX_X4(r0, r1, r2, r3, sKl + off);
                bL[nj * 2][0] = r0; bL[nj * 2][1] = r1;
                bL[nj * 2 + 1][0] = r2; bL[nj * 2 + 1][1] = r3;
            }
            #pragma unroll
            for (int nf = 0; nf < 8; nf++) MMA_BF16(sc[nf], aH, bH[nf]);
            #pragma unroll
            for (int nf = 0; nf < 8; nf++) MMA_BF16(sc[nf], aH, bL[nf]);
            #pragma unroll
            for (int nf = 0; nf < 8; nf++) MMA_BF16(sc[nf], aL, bH[nf]);
        }

        float mx0 = -1e30f, mx1 = -1e30f;
        #pragma unroll
        for (int nf = 0; nf < 8; nf++) {
            int col = kbase + nf * 8 + (lane & 3) * 2;
            int d00 = gR0 - col, d01 = d00 - 1;
            int d10 = gR0 + 8 - col, d11 = d10 - 1;
            sc[nf][0] = sc[nf][0] * scale + ((d00 >= 0 && d00 < WINDOW) ? 0.f : -1e9f);
            sc[nf][1] = sc[nf][1] * scale + ((d01 >= 0 && d01 < WINDOW) ? 0.f : -1e9f);
            sc[nf][2] = sc[nf][2] * scale + ((d10 >= 0 && d10 < WINDOW) ? 0.f : -1e9f);
            sc[nf][3] = sc[nf][3] * scale + ((d11 >= 0 && d11 < WINDOW) ? 0.f : -1e9f);
            mx0 = fmaxf(mx0, fmaxf(sc[nf][0], sc[nf][1]));
            mx1 = fmaxf(mx1, fmaxf(sc[nf][2], sc[nf][3]));
        }
        mx0 = fmaxf(mx0, __shfl_xor_sync(0xffffffffu, mx0, 1));
        mx0 = fmaxf(mx0, __shfl_xor_sync(0xffffffffu, mx0, 2));
        mx1 = fmaxf(mx1, __shfl_xor_sync(0xffffffffu, mx1, 1));
        mx1 = fmaxf(mx1, __shfl_xor_sync(0xffffffffu, mx1, 2));
        float mn0 = fmaxf(m0r, mx0), mn1 = fmaxf(m1r, mx1);
        float corr0 = __expf(m0r - mn0), corr1 = __expf(m1r - mn1);
        m0r = mn0; m1r = mn1;
        float rs0 = 0.f, rs1 = 0.f;
        #pragma unroll
        for (int nf = 0; nf < 8; nf++) {
            sc[nf][0] = __expf(sc[nf][0] - mn0);
            sc[nf][1] = __expf(sc[nf][1] - mn0);
            sc[nf][2] = __expf(sc[nf][2] - mn1);
            sc[nf][3] = __expf(sc[nf][3] - mn1);
            rs0 += sc[nf][0] + sc[nf][1];
            rs1 += sc[nf][2] + sc[nf][3];
        }
        rs0 += __shfl_xor_sync(0xffffffffu, rs0, 1);
        rs0 += __shfl_xor_sync(0xffffffffu, rs0, 2);
        rs1 += __shfl_xor_sync(0xffffffffu, rs1, 1);
        rs1 += __shfl_xor_sync(0xffffffffu, rs1, 2);
        l0r = l0r * corr0 + rs0;
        l1r = l1r * corr1 + rs1;
        #pragma unroll
        for (int nf = 0; nf < 16; nf++) {
            acc[nf][0] *= corr0; acc[nf][1] *= corr0;
            acc[nf][2] *= corr1; acc[nf][3] *= corr1;
        }

        uint32_t aPh[4][4], aPl[4][4];
        #pragma unroll
        for (int kt2 = 0; kt2 < 4; kt2++) {
            #pragma unroll
            for (int half = 0; half < 2; half++) {
                int nf = kt2 * 2 + half;
                __nv_bfloat162 h01 = __floats2bfloat162_rn(sc[nf][0], sc[nf][1]);
                __nv_bfloat162 h23 = __floats2bfloat162_rn(sc[nf][2], sc[nf][3]);
                float e0 = sc[nf][0] - __low2float(h01);
                float e1 = sc[nf][1] - __high2float(h01);
                float e2 = sc[nf][2] - __low2float(h23);
                float e3 = sc[nf][3] - __high2float(h23);
                __nv_bfloat162 l01 = __floats2bfloat162_rn(e0, e1);
                __nv_bfloat162 l23 = __floats2bfloat162_rn(e2, e3);
                aPh[kt2][half * 2 + 0] = *(uint32_t*)&h01;
                aPh[kt2][half * 2 + 1] = *(uint32_t*)&h23;
                aPl[kt2][half * 2 + 0] = *(uint32_t*)&l01;
                aPl[kt2][half * 2 + 1] = *(uint32_t*)&l23;
            }
        }

        #pragma unroll
        for (int kt2 = 0; kt2 < 4; kt2++) {
            uint32_t bb[16][2];
            uint32_t krow = (uint32_t)(kt2 * 16) + ((midx & 1) * 8) + rsel;
            #pragma unroll
            for (int nj = 0; nj < 8; nj++) {
                uint32_t j = (uint32_t)(nj * 2) + (midx >> 1);
                uint32_t off = krow * 256 + ((j ^ rsel) * 16);
                uint32_t r0, r1, r2, r3;
                LDMATRIX_X4_T(r0, r1, r2, r3, sVh + off);
                bb[nj * 2][0] = r0; bb[nj * 2][1] = r1;
                bb[nj * 2 + 1][0] = r2; bb[nj * 2 + 1][1] = r3;
            }
            #pragma unroll
            for (int nf = 0; nf < 16; nf++) MMA_BF16(acc[nf], aPh[kt2], bb[nf]);
            #pragma unroll
            for (int nf = 0; nf < 16; nf++) MMA_BF16(acc[nf], aPl[kt2], bb[nf]);
            #pragma unroll
            for (int nj = 0; nj < 8; nj++) {
                uint32_t j = (uint32_t)(nj * 2) + (midx >> 1);
                uint32_t off = krow * 256 + ((j ^ rsel) * 16);
                uint32_t r0, r1, r2, r3;
                LDMATRIX_X4_T(r0, r1, r2, r3, sVl + off);
                bb[nj * 2][0] = r0; bb[nj * 2][1] = r1;
                bb[nj * 2 + 1][0] = r2; bb[nj * 2 + 1][1] = r3;
            }
            #pragma unroll
            for (int nf = 0; nf < 16; nf++) MMA_BF16(acc[nf], aPh[kt2], bb[nf]);
        }
        __syncthreads();
    }

    float inv0 = 1.0f / l0r, inv1 = 1.0f / l1r;
    size_t row0 = qrow0 + wid * 16 + (lane >> 2);
    size_t row1 = row0 + 8;
    #pragma unroll
    for (int nf = 0; nf < 16; nf++) {
        int col = h * HDIM + nf * 8 + (lane & 3) * 2;
        float o0 = acc[nf][0] * inv0, o1 = acc[nf][1] * inv0;
        float o2 = acc[nf][2] * inv1, o3 = acc[nf][3] * inv1;
        uint32_t lo, hi;
        hi = pack_split(o0, o1, lo);
        *(uint32_t*)&Oh[row0 * DMODEL + col] = hi;
        *(uint32_t*)&Ol[row0 * DMODEL + col] = lo;
        hi = pack_split(o2, o3, lo);
        *(uint32_t*)&Oh[row1 * DMODEL + col] = hi;
        *(uint32_t*)&Ol[row1 * DMODEL + col] = lo;
    }
}

// ================= launch =================
extern "C" void kernel_launch(void* const* d_in, const int* in_sizes, int n_in,
                              void* d_out, int out_size) {
    const float* x  = (const float*)d_in[0];
    const float* Wq = (const float*)d_in[1];
    const float* Wk = (const float*)d_in[2];
    const float* Wv = (const float*)d_in[3];
    const float* Wo = (const float*)d_in[4];
    const float* bo = (const float*)d_in[5];
    float* out = (float*)d_out;

    bf16 *xh, *xl, *qh, *ql, *kh, *kl, *vh, *vl, *ath, *atl, *wqh, *wql, *woh, *wol;
    cudaGetSymbolAddress((void**)&xh,  g_xh);
    cudaGetSymbolAddress((void**)&xl,  g_xl);
    cudaGetSymbolAddress((void**)&qh,  g_qh);
    cudaGetSymbolAddress((void**)&ql,  g_ql);
    cudaGetSymbolAddress((void**)&kh,  g_kh);
    cudaGetSymbolAddress((void**)&kl,  g_kl);
    cudaGetSymbolAddress((void**)&vh,  g_vh);
    cudaGetSymbolAddress((void**)&vl,  g_vl);
    cudaGetSymbolAddress((void**)&ath, g_ath);
    cudaGetSymbolAddress((void**)&atl, g_atl);
    cudaGetSymbolAddress((void**)&wqh, g_wqt_h);
    cudaGetSymbolAddress((void**)&wql, g_wqt_l);
    cudaGetSymbolAddress((void**)&woh, g_wot_h);
    cudaGetSymbolAddress((void**)&wol, g_wot_l);

    const int GEMM_SMEM = 98304;
    cudaFuncSetAttribute(gemm_kernel<true>,
                         cudaFuncAttributeMaxDynamicSharedMemorySize, GEMM_SMEM);
    cudaFuncSetAttribute(gemm_kernel<false>,
                         cudaFuncAttributeMaxDynamicSharedMemorySize, GEMM_SMEM);
    const int ATTN_SMEM = 196608;
    cudaFuncSetAttribute(attn_mma_kernel,
                         cudaFuncAttributeMaxDynamicSharedMemorySize, ATTN_SMEM);

    // launches 0..4: prep
    rope_table_kernel<<<(L_SEQ * 32 + 255) / 256, 256>>>();
    split_kernel<<<(BROWS * DMODEL) / 256, 256>>>(x, xh, xl, BROWS * DMODEL);
    dim3 tb(32, 8);
    tsplit_kernel<<<dim3(DMODEL / 32, KDIM / 32), tb>>>(Wq, wqh, wql, DMODEL, 0);
    tsplit_kv_kernel<<<dim3(HDIM / 32, KDIM / 32, 2), tb>>>(Wk, Wv);
    tsplit_kernel<<<dim3(DMODEL / 32, KDIM / 32), tb>>>(Wo, woh, wol, DMODEL, 0);

    // launch 5: fused QKV projection + RoPE + split (profiled by ncu -s 5 -c 1)
    gemm_kernel<true><<<dim3(18, BROWS / 128), 256, GEMM_SMEM>>>(nullptr, nullptr);

    // launch 6: tensor-core attention -> bf16 hi/lo
    dim3 ga(L_SEQ / 128, NHEADS, 2);
    attn_mma_kernel<<<ga, 256, ATTN_SMEM>>>(qh, ql, kh, kl, vh, vl, ath, atl);

    // launch 7: output projection + bias
    gemm_kernel<false><<<dim3(16, BROWS / 128), 256, GEMM_SMEM>>>(bo, out);
}

// round 6
// speedup vs baseline: 3.7194x; 1.3727x over previous
#include <cuda_runtime.h>
#include <cuda_fp16.h>
#include <math.h>
#include <stdint.h>

#define L_SEQ   2048
#define DMODEL  2048
#define NHEADS  16
#define HDIM    128
#define WINDOW  512
#define BROWS   4096   // B * L
#define KDIM    2048

typedef __half h16;

// ================= scratch =================
__device__ float g_cs[L_SEQ * 64];          // (cos,sin) interleaved
__device__ h16 g_xh[BROWS * DMODEL];
__device__ h16 g_xl[BROWS * DMODEL];
__device__ h16 g_qh[BROWS * DMODEL];
__device__ h16 g_ql[BROWS * DMODEL];
__device__ h16 g_kh[BROWS * HDIM];
__device__ h16 g_vh[BROWS * HDIM];
__device__ h16 g_ath[BROWS * DMODEL];
__device__ h16 g_atl[BROWS * DMODEL];
__device__ h16 g_wqt_h[DMODEL * KDIM];
__device__ h16 g_wot_h[DMODEL * KDIM];
__device__ h16 g_wkvt_h[256 * KDIM];

// ================= helpers =================
__device__ __forceinline__ uint32_t smem_u32(const void* p) {
    uint32_t a;
    asm("{ .reg .u64 t; cvta.to.shared.u64 t, %1; cvt.u32.u64 %0, t; }" : "=r"(a) : "l"(p));
    return a;
}
#define CP_ASYNC16(saddr, gptr) \
    asm volatile("cp.async.cg.shared.global [%0], [%1], 16;" :: "r"(saddr), "l"(gptr))
#define CP_COMMIT()  asm volatile("cp.async.commit_group;" ::: "memory")
#define CP_WAIT0()   asm volatile("cp.async.wait_group 0;" ::: "memory")
#define CP_WAIT1()   asm volatile("cp.async.wait_group 1;" ::: "memory")

#define LDMATRIX_X4(r0, r1, r2, r3, addr) \
    asm volatile("ldmatrix.sync.aligned.m8n8.x4.shared.b16 {%0,%1,%2,%3}, [%4];" \
        : "=r"(r0), "=r"(r1), "=r"(r2), "=r"(r3) : "r"(addr))

#define LDMATRIX_X4_T(r0, r1, r2, r3, addr) \
    asm volatile("ldmatrix.sync.aligned.m8n8.x4.trans.shared.b16 {%0,%1,%2,%3}, [%4];" \
        : "=r"(r0), "=r"(r1), "=r"(r2), "=r"(r3) : "r"(addr))

#define MMA_F16(c, a, b) \
    asm volatile("mma.sync.aligned.m16n8k16.row.col.f32.f16.f16.f32 " \
        "{%0,%1,%2,%3}, {%4,%5,%6,%7}, {%8,%9}, {%0,%1,%2,%3};" \
        : "+f"((c)[0]), "+f"((c)[1]), "+f"((c)[2]), "+f"((c)[3]) \
        : "r"((a)[0]), "r"((a)[1]), "r"((a)[2]), "r"((a)[3]), "r"((b)[0]), "r"((b)[1]))

__device__ __forceinline__ uint32_t pack_split(float a, float b, uint32_t& lo) {
    __half2 h = __floats2half2_rn(a, b);
    __half2 l = __floats2half2_rn(a - __low2float(h), b - __high2float(h));
    lo = *(uint32_t*)&l;
    return *(uint32_t*)&h;
}

// ================= prep kernels =================
__global__ void rope_table_kernel() {
    int idx = blockIdx.x * blockDim.x + threadIdx.x;
    if (idx >= L_SEQ * 32) return;
    int pos = idx >> 5;
    int i = idx & 31;
    double inv = exp(-log(10000.0) * ((double)(2 * i) / 64.0));
    double th = (double)pos * inv;
    g_cs[pos * 64 + i * 2 + 0] = (float)cos(th);
    g_cs[pos * 64 + i * 2 + 1] = (float)sin(th);
}

__global__ void split_kernel(const float* __restrict__ in,
                             h16* __restrict__ hi, h16* __restrict__ lo, int n) {
    int idx = blockIdx.x * blockDim.x + threadIdx.x;
    if (idx >= n) return;
    float v = in[idx];
    h16 h = __float2half_rn(v);
    hi[idx] = h;
    lo[idx] = __float2half_rn(v - __half2float(h));
}

// W [K][N] fp32 -> Th [ro+N][KDIM] fp16 hi (transposed)
__global__ void thalf_kernel(const float* __restrict__ W,
                             h16* __restrict__ Th, int N, int ro) {
    __shared__ float tile[32][33];
    int n0 = blockIdx.x * 32, k0 = blockIdx.y * 32;
    int tx = threadIdx.x, ty = threadIdx.y;
    #pragma unroll
    for (int i = ty; i < 32; i += 8)
        tile[i][tx] = W[(size_t)(k0 + i) * N + n0 + tx];
    __syncthreads();
    #pragma unroll
    for (int i = ty; i < 32; i += 8)
        Th[(size_t)(ro + n0 + i) * KDIM + k0 + tx] = __float2half_rn(tile[tx][i]);
}

__global__ void thalf_kv_kernel(const float* __restrict__ Wk,
                                const float* __restrict__ Wv) {
    __shared__ float tile[32][33];
    const float* W = blockIdx.z ? Wv : Wk;
    int ro = blockIdx.z ? 128 : 0;
    int n0 = blockIdx.x * 32, k0 = blockIdx.y * 32;
    int tx = threadIdx.x, ty = threadIdx.y;
    #pragma unroll
    for (int i = ty; i < 32; i += 8)
        tile[i][tx] = W[(size_t)(k0 + i) * HDIM + n0 + tx];
    __syncthreads();
    #pragma unroll
    for (int i = ty; i < 32; i += 8)
        g_wkvt_h[(size_t)(ro + n0 + i) * KDIM + k0 + tx] = __float2half_rn(tile[tx][i]);
}

// ================= mma.sync fp16 2-pass GEMM, 3-stage pipeline =================
// C = (Ah + Al) * Bh^T ; QKV variant fuses rope + fp16 hi/lo split epilogue.
template <bool QKV>
__global__ void __launch_bounds__(256, 2)
gemm_kernel(const float* __restrict__ bias, float* __restrict__ Cout) {
    extern __shared__ char smem[];
    const uint32_t smb = smem_u32(smem);
    const int tid = threadIdx.x;
    const int wid = tid >> 5;
    const int lane = tid & 31;
    const int wm = wid >> 1;          // 0..3
    const int wn = wid & 1;           // 0..1
    const uint32_t midx = lane >> 3;
    const uint32_t rsel = lane & 7;

    const int m0 = blockIdx.y * 128;
    const h16* Ah = QKV ? g_xh : g_ath;
    const h16* Al = QKV ? g_xl : g_atl;
    const h16* Bh;
    int n0;
    h16 *OutH = nullptr, *OutL = nullptr;
    int strideO = 0, colBase = 0;
    bool do_rope = false;
    if (QKV) {
        if ((int)blockIdx.x < 16) {
            Bh = g_wqt_h; n0 = blockIdx.x * 128;
            OutH = g_qh; OutL = g_ql; strideO = DMODEL; colBase = n0; do_rope = true;
        } else if (blockIdx.x == 16) {
            Bh = g_wkvt_h; n0 = 0;
            OutH = g_kh; OutL = nullptr; strideO = HDIM; colBase = 0; do_rope = true;
        } else {
            Bh = g_wkvt_h; n0 = 128;
            OutH = g_vh; OutL = nullptr; strideO = HDIM; colBase = 0; do_rope = false;
        }
    } else {
        Bh = g_wot_h; n0 = blockIdx.x * 128;
    }

    const h16* srcs[3] = {
        Ah + (size_t)m0 * KDIM, Al + (size_t)m0 * KDIM, Bh + (size_t)n0 * KDIM };

    const int fr = tid >> 2;
    const uint32_t fkt = (uint32_t)(tid & 3);
    const int fc0 = (tid & 3) * 8;

    auto fill = [&](int kc, uint32_t sbase) {
        #pragma unroll
        for (int m = 0; m < 3; m++)
            #pragma unroll
            for (int half = 0; half < 2; half++) {
                int rr = fr + half * 64;
                uint32_t off = ((uint32_t)(rr >> 3) * 4 + fkt) * 128
                             + ((uint32_t)((rr & 7) ^ fkt) * 16);
                CP_ASYNC16(sbase + m * 8192 + off,
                           srcs[m] + (size_t)rr * KDIM + kc * 32 + fc0);
            }
    };

    float acc[2][8][4];
    #pragma unroll
    for (int i = 0; i < 2; i++)
        #pragma unroll
        for (int j = 0; j < 8; j++)
            #pragma unroll
            for (int c = 0; c < 4; c++) acc[i][j][c] = 0.0f;

    fill(0, smb);          CP_COMMIT();
    fill(1, smb + 24576);  CP_COMMIT();

    const int NK = KDIM / 32;
    for (int kc = 0; kc < NK; kc++) {
        if (kc + 1 < NK) CP_WAIT1(); else CP_WAIT0();
        __syncthreads();
        if (kc + 2 < NK) {
            fill(kc + 2, smb + ((kc + 2) % 3) * 24576);
            CP_COMMIT();
        }

        const uint32_t sb = smb + (kc % 3) * 24576;
        const uint32_t aBaseH = sb;
        const uint32_t aBaseL = sb + 8192;
        const uint32_t bBaseH = sb + 16384;

        #pragma unroll
        for (int kt = 0; kt < 2; kt++) {
            uint32_t aF[2][4], bF[8][2];
            const uint32_t TkA = (uint32_t)(kt * 2) + (midx >> 1);
            const uint32_t TkB = (uint32_t)(kt * 2) + (midx & 1);
            // B hi
            #pragma unroll
            for (int nj = 0; nj < 4; nj++) {
                uint32_t Tn = (uint32_t)(wn * 8 + nj * 2) + (midx >> 1);
                uint32_t addr = bBaseH + (Tn * 4 + TkB) * 128 + ((rsel ^ TkB) * 16);
                uint32_t r0, r1, r2, r3;
                LDMATRIX_X4(r0, r1, r2, r3, addr);
                bF[nj * 2][0] = r0; bF[nj * 2][1] = r1;
                bF[nj * 2 + 1][0] = r2; bF[nj * 2 + 1][1] = r3;
            }
            // A hi -> pass hh
            #pragma unroll
            for (int mi = 0; mi < 2; mi++) {
                uint32_t Tm = (uint32_t)(wm * 4 + mi * 2) + (midx & 1);
                uint32_t addr = aBaseH + (Tm * 4 + TkA) * 128 + ((rsel ^ TkA) * 16);
                LDMATRIX_X4(aF[mi][0], aF[mi][1], aF[mi][2], aF[mi][3], addr);
            }
            #pragma unroll
            for (int mi = 0; mi < 2; mi++)
                #pragma unroll
                for (int nf = 0; nf < 8; nf++)
                    MMA_F16(acc[mi][nf], aF[mi], bF[nf]);
            // A lo -> pass lh
            #pragma unroll
            for (int mi = 0; mi < 2; mi++) {
                uint32_t Tm = (uint32_t)(wm * 4 + mi * 2) + (midx & 1);
                uint32_t addr = aBaseL + (Tm * 4 + TkA) * 128 + ((rsel ^ TkA) * 16);
                LDMATRIX_X4(aF[mi][0], aF[mi][1], aF[mi][2], aF[mi][3], addr);
            }
            #pragma unroll
            for (int mi = 0; mi < 2; mi++)
                #pragma unroll
                for (int nf = 0; nf < 8; nf++)
                    MMA_F16(acc[mi][nf], aF[mi], bF[nf]);
        }
        __syncthreads();
    }

    // ================= epilogue =================
    if (!QKV) {
        #pragma unroll
        for (int mi = 0; mi < 2; mi++) {
            int row = m0 + wm * 32 + mi * 16 + (lane >> 2);
            #pragma unroll
            for (int nf = 0; nf < 8; nf++) {
                int col = n0 + wn * 64 + nf * 8 + (lane & 3) * 2;
                float b0 = bias[col], b1 = bias[col + 1];
                float2 v0, v1;
                v0.x = acc[mi][nf][0] + b0; v0.y = acc[mi][nf][1] + b1;
                v1.x = acc[mi][nf][2] + b0; v1.y = acc[mi][nf][3] + b1;
                *(float2*)&Cout[(size_t)row * DMODEL + col] = v0;
                *(float2*)&Cout[(size_t)(row + 8) * DMODEL + col] = v1;
            }
        }
        return;
    }

    if (do_rope && wn == 0) {
        #pragma unroll
        for (int mi = 0; mi < 2; mi++) {
            int r0 = m0 + wm * 32 + mi * 16 + (lane >> 2);
            int pos0 = r0 & (L_SEQ - 1);
            int pos1 = (r0 + 8) & (L_SEQ - 1);
            #pragma unroll
            for (int nf = 0; nf < 4; nf++) {
                int c = nf * 8 + (lane & 3) * 2;
                float2 csA0 = *(float2*)&g_cs[pos0 * 64 + c * 2];
                float2 csB0 = *(float2*)&g_cs[pos0 * 64 + c * 2 + 2];
                float2 csA1 = *(float2*)&g_cs[pos1 * 64 + c * 2];
                float2 csB1 = *(float2*)&g_cs[pos1 * 64 + c * 2 + 2];
                float x1, x2;
                x1 = acc[mi][nf][0]; x2 = acc[mi][nf + 4][0];
                acc[mi][nf][0]     = x1 * csA0.x - x2 * csA0.y;
                acc[mi][nf + 4][0] = x1 * csA0.y + x2 * csA0.x;
                x1 = acc[mi][nf][1]; x2 = acc[mi][nf + 4][1];
                acc[mi][nf][1]     = x1 * csB0.x - x2 * csB0.y;
                acc[mi][nf + 4][1] = x1 * csB0.y + x2 * csB0.x;
                x1 = acc[mi][nf][2]; x2 = acc[mi][nf + 4][2];
                acc[mi][nf][2]     = x1 * csA1.x - x2 * csA1.y;
                acc[mi][nf + 4][2] = x1 * csA1.y + x2 * csA1.x;
                x1 = acc[mi][nf][3]; x2 = acc[mi][nf + 4][3];
                acc[mi][nf][3]     = x1 * csB1.x - x2 * csB1.y;
                acc[mi][nf + 4][3] = x1 * csB1.y + x2 * csB1.x;
            }
        }
    }

    #pragma unroll
    for (int mi = 0; mi < 2; mi++) {
        int row = m0 + wm * 32 + mi * 16 + (lane >> 2);
        #pragma unroll
        for (int nf = 0; nf < 8; nf++) {
            int cl = colBase + wn * 64 + nf * 8 + (lane & 3) * 2;
            uint32_t lo, hi;
            hi = pack_split(acc[mi][nf][0], acc[mi][nf][1], lo);
            *(uint32_t*)&OutH[(size_t)row * strideO + cl] = hi;
            if (OutL) *(uint32_t*)&OutL[(size_t)row * strideO + cl] = lo;
            hi = pack_split(acc[mi][nf][2], acc[mi][nf][3], lo);
            *(uint32_t*)&OutH[(size_t)(row + 8) * strideO + cl] = hi;
            if (OutL) *(uint32_t*)&OutL[(size_t)(row + 8) * strideO + cl] = lo;
        }
    }
}

// ================= tensor-core sliding-window flash attention (fp16 2-pass) ====
__global__ void __launch_bounds__(256, 1)
attn_mma_kernel(const h16* __restrict__ Qh, const h16* __restrict__ Ql,
                const h16* __restrict__ Kh, const h16* __restrict__ Vh,
                h16* __restrict__ Oh, h16* __restrict__ Ol) {
    extern __shared__ char smem[];
    const uint32_t smb = smem_u32(smem);
    const uint32_t QH_OFF = 0, QL_OFF = 32768, KV_OFF = 65536, KV_STRIDE = 32768;
    const int tid = threadIdx.x, wid = tid >> 5, lane = tid & 31;
    const uint32_t midx = lane >> 3, rsel = lane & 7;
    const int qt = blockIdx.x, h = blockIdx.y, b = blockIdx.z;
    const int qbase = qt * 128;
    const size_t qrow0 = (size_t)(b * L_SEQ + qbase);
    const float scale = 0.08838834764831845f;

    {
        const h16* srcQ[2] = {
            Qh + qrow0 * DMODEL + h * HDIM, Ql + qrow0 * DMODEL + h * HDIM };
        #pragma unroll
        for (int m = 0; m < 2; m++) {
            uint32_t base = smb + (m ? QL_OFF : QH_OFF);
            #pragma unroll
            for (int i = 0; i < 8; i++) {
                int cid = tid + i * 256;
                int r = cid >> 4, j = cid & 15;
                uint32_t off = ((uint32_t)(r >> 3) * 16 + j) * 128
                             + ((uint32_t)((r & 7) ^ (j & 7)) * 16);
                CP_ASYNC16(base + off, srcQ[m] + (size_t)r * DMODEL + j * 8);
            }
        }
    }

    int t0 = qbase - (WINDOW - 1);
    if (t0 < 0) t0 = 0;
    t0 >>= 6;
    const int t1 = (qbase + 127) >> 6;

    auto fill_kv = [&](int t, uint32_t sb) {
        const int kbase = t * 64;
        const size_t rowb = (size_t)(b * L_SEQ + kbase);
        const h16* srcs[2] = { Kh + rowb * HDIM, Vh + rowb * HDIM };
        #pragma unroll
        for (int m = 0; m < 2; m++) {
            uint32_t base = sb + m * 16384;
            #pragma unroll
            for (int i = 0; i < 4; i++) {
                int cid = tid + i * 256;
                int r = cid >> 4, j = cid & 15;
                uint32_t off;
                if (m == 0)
                    off = ((uint32_t)(r >> 3) * 16 + j) * 128
                        + ((uint32_t)((r & 7) ^ (j & 7)) * 16);
                else
                    off = (uint32_t)r * 256 + ((uint32_t)(j ^ (r & 7)) * 16);
                CP_ASYNC16(base + off, srcs[m] + (size_t)r * HDIM + j * 8);
            }
        }
    };
    fill_kv(t0, smb + KV_OFF);
    CP_COMMIT();

    float acc[16][4];
    #pragma unroll
    for (int i = 0; i < 16; i++)
        #pragma unroll
        for (int c = 0; c < 4; c++) acc[i][c] = 0.0f;
    float m0r = -1e30f, m1r = -1e30f, l0r = 0.0f, l1r = 0.0f;

    const int gR0 = qbase + wid * 16 + (lane >> 2);
    const uint32_t sQh = smb + QH_OFF, sQl = smb + QL_OFF;

    for (int t = t0; t <= t1; t++) {
        if (t < t1) {
            fill_kv(t + 1, smb + KV_OFF + ((t + 1) & 1) * KV_STRIDE);
            CP_COMMIT();
            CP_WAIT1();
        } else {
            CP_WAIT0();
        }
        __syncthreads();

        const uint32_t sKV = smb + KV_OFF + (t & 1) * KV_STRIDE;
        const uint32_t sKh = sKV;
        const uint32_t sVh = sKV + 16384;
        const int kbase = t * 64;

        float sc[8][4];
        #pragma unroll
        for (int i = 0; i < 8; i++)
            #pragma unroll
            for (int c = 0; c < 4; c++) sc[i][c] = 0.0f;

        const uint32_t TmA = (uint32_t)(wid * 2) + (midx & 1);
        #pragma unroll
        for (int ks = 0; ks < 8; ks++) {
            uint32_t aH[4], aL[4], bH[8][2];
            uint32_t TkA = (uint32_t)(ks * 2) + (midx >> 1);
            uint32_t offA = (TmA * 16 + TkA) * 128 + ((rsel ^ (TkA & 7)) * 16);
            LDMATRIX_X4(aH[0], aH[1], aH[2], aH[3], sQh + offA);
            LDMATRIX_X4(aL[0], aL[1], aL[2], aL[3], sQl + offA);
            uint32_t TkB = (uint32_t)(ks * 2) + (midx & 1);
            #pragma unroll
            for (int nj = 0; nj < 4; nj++) {
                uint32_t Tn = (uint32_t)(nj * 2) + (midx >> 1);
                uint32_t off = (Tn * 16 + TkB) * 128 + ((rsel ^ (TkB & 7)) * 16);
                uint32_t r0, r1, r2, r3;
                LDMATRIX_X4(r0, r1, r2, r3, sKh + off);
                bH[nj * 2][0] = r0; bH[nj * 2][1] = r1;
                bH[nj * 2 + 1][0] = r2; bH[nj * 2 + 1][1] = r3;
            }
            #pragma unroll
            for (int nf = 0; nf < 8; nf++) MMA_F16(sc[nf], aH, bH[nf]);
            #pragma unroll
            for (int nf = 0; nf < 8; nf++) MMA_F16(sc[nf], aL, bH[nf]);
        }

        float mx0 = -1e30f, mx1 = -1e30f;
        #pragma unroll
        for (int nf = 0; nf < 8; nf++) {
            int col = kbase + nf * 8 + (lane & 3) * 2;
            int d00 = gR0 - col, d01 = d00 - 1;
            int d10 = gR0 + 8 - col, d11 = d10 - 1;
            sc[nf][0] = sc[nf][0] * scale + ((d00 >= 0 && d00 < WINDOW) ? 0.f : -1e9f);
            sc[nf][1] = sc[nf][1] * scale + ((d01 >= 0 && d01 < WINDOW) ? 0.f : -1e9f);
            sc[nf][2] = sc[nf][2] * scale + ((d10 >= 0 && d10 < WINDOW) ? 0.f : -1e9f);
            sc[nf][3] = sc[nf][3] * scale + ((d11 >= 0 && d11 < WINDOW) ? 0.f : -1e9f);
            mx0 = fmaxf(mx0, fmaxf(sc[nf][0], sc[nf][1]));
            mx1 = fmaxf(mx1, fmaxf(sc[nf][2], sc[nf][3]));
        }
        mx0 = fmaxf(mx0, __shfl_xor_sync(0xffffffffu, mx0, 1));
        mx0 = fmaxf(mx0, __shfl_xor_sync(0xffffffffu, mx0, 2));
        mx1 = fmaxf(mx1, __shfl_xor_sync(0xffffffffu, mx1, 1));
        mx1 = fmaxf(mx1, __shfl_xor_sync(0xffffffffu, mx1, 2));
        float mn0 = fmaxf(m0r, mx0), mn1 = fmaxf(m1r, mx1);
        float corr0 = __expf(m0r - mn0), corr1 = __expf(m1r - mn1);
        m0r = mn0; m1r = mn1;
        float rs0 = 0.f, rs1 = 0.f;
        #pragma unroll
        for (int nf = 0; nf < 8; nf++) {
            sc[nf][0] = __expf(sc[nf][0] - mn0);
            sc[nf][1] = __expf(sc[nf][1] - mn0);
            sc[nf][2] = __expf(sc[nf][2] - mn1);
            sc[nf][3] = __expf(sc[nf][3] - mn1);
            rs0 += sc[nf][0] + sc[nf][1];
            rs1 += sc[nf][2] + sc[nf][3];
        }
        rs0 += __shfl_xor_sync(0xffffffffu, rs0, 1);
        rs0 += __shfl_xor_sync(0xffffffffu, rs0, 2);
        rs1 += __shfl_xor_sync(0xffffffffu, rs1, 1);
        rs1 += __shfl_xor_sync(0xffffffffu, rs1, 2);
        l0r = l0r * corr0 + rs0;
        l1r = l1r * corr1 + rs1;
        #pragma unroll
        for (int nf = 0; nf < 16; nf++) {
            acc[nf][0] *= corr0; acc[nf][1] *= corr0;
            acc[nf][2] *= corr1; acc[nf][3] *= corr1;
        }

        // P -> fp16 hi/lo A-frags
        uint32_t aPh[4][4], aPl[4][4];
        #pragma unroll
        for (int kt2 = 0; kt2 < 4; kt2++) {
            #pragma unroll
            for (int half = 0; half < 2; half++) {
                int nf = kt2 * 2 + half;
                uint32_t lo01, lo23;
                uint32_t hi01 = pack_split(sc[nf][0], sc[nf][1], lo01);
                uint32_t hi23 = pack_split(sc[nf][2], sc[nf][3], lo23);
                aPh[kt2][half * 2 + 0] = hi01;
                aPh[kt2][half * 2 + 1] = hi23;
                aPl[kt2][half * 2 + 0] = lo01;
                aPl[kt2][half * 2 + 1] = lo23;
            }
        }

        // PV: (Ph + Pl) * Vh, V fragments loaded once per kt2
        #pragma unroll
        for (int kt2 = 0; kt2 < 4; kt2++) {
            uint32_t bb[16][2];
            uint32_t krow = (uint32_t)(kt2 * 16) + ((midx & 1) * 8) + rsel;
            #pragma unroll
            for (int nj = 0; nj < 8; nj++) {
                uint32_t j = (uint32_t)(nj * 2) + (midx >> 1);
                uint32_t off = krow * 256 + ((j ^ rsel) * 16);
                uint32_t r0, r1, r2, r3;
                LDMATRIX_X4_T(r0, r1, r2, r3, sVh + off);
                bb[nj * 2][0] = r0; bb[nj * 2][1] = r1;
                bb[nj * 2 + 1][0] = r2; bb[nj * 2 + 1][1] = r3;
            }
            #pragma unroll
            for (int nf = 0; nf < 16; nf++) MMA_F16(acc[nf], aPh[kt2], bb[nf]);
            #pragma unroll
            for (int nf = 0; nf < 16; nf++) MMA_F16(acc[nf], aPl[kt2], bb[nf]);
        }
        __syncthreads();
    }

    float inv0 = 1.0f / l0r, inv1 = 1.0f / l1r;
    size_t row0 = qrow0 + wid * 16 + (lane >> 2);
    size_t row1 = row0 + 8;
    #pragma unroll
    for (int nf = 0; nf < 16; nf++) {
        int col = h * HDIM + nf * 8 + (lane & 3) * 2;
        uint32_t lo, hi;
        hi = pack_split(acc[nf][0] * inv0, acc[nf][1] * inv0, lo);
        *(uint32_t*)&Oh[row0 * DMODEL + col] = hi;
        *(uint32_t*)&Ol[row0 * DMODEL + col] = lo;
        hi = pack_split(acc[nf][2] * inv1, acc[nf][3] * inv1, lo);
        *(uint32_t*)&Oh[row1 * DMODEL + col] = hi;
        *(uint32_t*)&Ol[row1 * DMODEL + col] = lo;
    }
}

// ================= launch =================
extern "C" void kernel_launch(void* const* d_in, const int* in_sizes, int n_in,
                              void* d_out, int out_size) {
    const float* x  = (const float*)d_in[0];
    const float* Wq = (const float*)d_in[1];
    const float* Wk = (const float*)d_in[2];
    const float* Wv = (const float*)d_in[3];
    const float* Wo = (const float*)d_in[4];
    const float* bo = (const float*)d_in[5];
    float* out = (float*)d_out;

    h16 *xh, *xl, *qh, *ql, *kh, *vh, *ath, *atl, *wqh, *woh;
    cudaGetSymbolAddress((void**)&xh,  g_xh);
    cudaGetSymbolAddress((void**)&xl,  g_xl);
    cudaGetSymbolAddress((void**)&qh,  g_qh);
    cudaGetSymbolAddress((void**)&ql,  g_ql);
    cudaGetSymbolAddress((void**)&kh,  g_kh);
    cudaGetSymbolAddress((void**)&vh,  g_vh);
    cudaGetSymbolAddress((void**)&ath, g_ath);
    cudaGetSymbolAddress((void**)&atl, g_atl);
    cudaGetSymbolAddress((void**)&wqh, g_wqt_h);
    cudaGetSymbolAddress((void**)&woh, g_wot_h);

    const int GEMM_SMEM = 73728;
    cudaFuncSetAttribute(gemm_kernel<true>,
                         cudaFuncAttributeMaxDynamicSharedMemorySize, GEMM_SMEM);
    cudaFuncSetAttribute(gemm_kernel<false>,
                         cudaFuncAttributeMaxDynamicSharedMemorySize, GEMM_SMEM);
    const int ATTN_SMEM = 131072;
    cudaFuncSetAttribute(attn_mma_kernel,
                         cudaFuncAttributeMaxDynamicSharedMemorySize, ATTN_SMEM);

    // prep
    rope_table_kernel<<<(L_SEQ * 32 + 255) / 256, 256>>>();
    split_kernel<<<(BROWS * DMODEL) / 256, 256>>>(x, xh, xl, BROWS * DMODEL);
    dim3 tb(32, 8);
    thalf_kernel<<<dim3(DMODEL / 32, KDIM / 32), tb>>>(Wq, wqh, DMODEL, 0);
    thalf_kv_kernel<<<dim3(HDIM / 32, KDIM / 32, 2), tb>>>(Wk, Wv);
    thalf_kernel<<<dim3(DMODEL / 32, KDIM / 32), tb>>>(Wo, woh, DMODEL, 0);

    // launch 5: fused QKV projection + RoPE + split
    gemm_kernel<true><<<dim3(18, BROWS / 128), 256, GEMM_SMEM>>>(nullptr, nullptr);

    // launch 6: tensor-core attention
    dim3 ga(L_SEQ / 128, NHEADS, 2);
    attn_mma_kernel<<<ga, 256, ATTN_SMEM>>>(qh, ql, kh, vh, ath, atl);

    // launch 7: output projection + bias
    gemm_kernel<false><<<dim3(16, BROWS / 128), 256, GEMM_SMEM>>>(bo, out);
}